// round 3
// baseline (speedup 1.0000x reference)
#include <cuda_runtime.h>
#include <cuda_bf16.h>

// Problem constants
#define N_   100000
#define E_   1600000
#define IN_  64
#define H_   128
#define O_   64

// ---------------- scratch (device globals; no allocation allowed) -------------
__device__ float g_degp[N_];
__device__ float g_degn[N_];
__device__ float g_dinvp[N_];
__device__ float g_dinvn[N_];
__device__ float g_hps[N_ * H_];   // hp * dinvp  (layer-1 pos, pre-scaled)
__device__ float g_hns[N_ * H_];   // hn * dinvn
__device__ float g_h  [N_ * H_];   // layer-1 accumulator -> hidden (pre-relu)
__device__ float g_gps[N_ * O_];   // gp * dinvp  (layer-2)
__device__ float g_gns[N_ * O_];

// ---------------- helpers ------------------------------------------------------
__device__ __forceinline__ void red_add_v4(float* p, float a, float b, float c, float d) {
    asm volatile("red.global.add.v4.f32 [%0], {%1,%2,%3,%4};"
                 :: "l"(p), "f"(a), "f"(b), "f"(c), "f"(d) : "memory");
}

__device__ __forceinline__ void fma2(unsigned long long& acc,
                                     unsigned long long w,
                                     unsigned long long xx) {
    asm("fma.rn.f32x2 %0, %1, %2, %0;" : "+l"(acc) : "l"(w), "l"(xx));
}

__device__ __forceinline__ unsigned long long pack2(float x) {
    unsigned long long r;
    asm("mov.b64 %0, {%1, %1};" : "=l"(r) : "f"(x));
    return r;
}

__device__ __forceinline__ void unpack2(unsigned long long v, float& lo, float& hi) {
    asm("mov.b64 {%0, %1}, %2;" : "=f"(lo), "=f"(hi) : "l"(v));
}

// ---------------- degree / dinv -----------------------------------------------
__global__ void k_zero_deg(int n) {
    int i = blockIdx.x * blockDim.x + threadIdx.x;
    if (i < n) { g_degp[i] = 0.f; g_degn[i] = 0.f; }
}

__global__ void k_deg(const int* __restrict__ ei, const float* __restrict__ w, int E) {
    int e = blockIdx.x * blockDim.x + threadIdx.x;
    if (e >= E) return;
    float we = w[e];
    int t = ei[E + e];
    if (we > 0.f)      atomicAdd(&g_degp[t], we);
    else if (we < 0.f) atomicAdd(&g_degn[t], -we);
}

__global__ void k_dinv(int n) {
    int i = blockIdx.x * blockDim.x + threadIdx.x;
    if (i < n) {
        g_dinvp[i] = rsqrtf(g_degp[i] + 1.0f);
        g_dinvn[i] = rsqrtf(g_degn[i] + 1.0f);
    }
}

// ================ GEMM layer 1: x[N,64] -> (hps,hns,h)[N,128] ==================
// 256 threads: tx = tid&15 -> 8 output cols (4 col-pairs), ty = tid>>4 -> 4 rows.
// smem weights pre-packed per col-pair: (wp0,wp1,wn0,wn1) float4 per (k, c2).
#define SMEM1 (64 * 64 * 16 + 64 * IN_ * 4)   // 64KB w4 + 16KB x = 80KB
__global__ __launch_bounds__(256, 2) void k_gemm1(
    const float* __restrict__ x,
    const float* __restrict__ W1p, const float* __restrict__ b1p,
    const float* __restrict__ W1n, const float* __restrict__ b1n, int n)
{
    extern __shared__ char sm[];
    ulonglong2* w4 = (ulonglong2*)sm;                  // [64 k][64 c2]
    float* xs = (float*)(sm + 64 * 64 * 16);           // [64 row][64 k]
    const int tid = threadIdx.x;
    const int tx = tid & 15;          // col group: cols 8*tx .. 8*tx+7
    const int ty = tid >> 4;          // row group: rows 4*ty .. 4*ty+3
    const int c2base = tx * 4;        // col-pair base (pairs of cols)
    const int base = blockIdx.x * 64;

    // weights: w4[k][c2] = (W1p[2c2][k], W1p[2c2+1][k], W1n[2c2][k], W1n[2c2+1][k])
    for (int i = tid; i < 64 * 64; i += 256) {
        int k  = i >> 6;
        int c2 = i & 63;
        union { float4 f; ulonglong2 u; } cv;
        cv.f = make_float4(W1p[(2 * c2) * IN_ + k], W1p[(2 * c2 + 1) * IN_ + k],
                           W1n[(2 * c2) * IN_ + k], W1n[(2 * c2 + 1) * IN_ + k]);
        w4[k * 64 + c2] = cv.u;
    }
    // x tile, row-major [64][64]
    for (int i = tid; i < 64 * (IN_ / 4); i += 256) {
        int r = i >> 4;
        int row = base + r;
        float4 v = make_float4(0.f, 0.f, 0.f, 0.f);
        if (row < n) v = ((const float4*)x)[row * (IN_ / 4) + (i & 15)];
        ((float4*)xs)[i] = v;
    }
    __syncthreads();

    unsigned long long accp[4][4], accn[4][4];
    #pragma unroll
    for (int j = 0; j < 4; j++)
        #pragma unroll
        for (int c = 0; c < 4; c++) { accp[j][c] = 0ull; accn[j][c] = 0ull; }

    const float* xrow = xs + (4 * ty) * IN_;
    for (int k4 = 0; k4 < IN_ / 4; k4++) {
        float4 xv[4];
        #pragma unroll
        for (int j = 0; j < 4; j++)
            xv[j] = *(const float4*)&xrow[j * IN_ + 4 * k4];
        #pragma unroll
        for (int kk = 0; kk < 4; kk++) {
            int k = 4 * k4 + kk;
            ulonglong2 wv[4];
            #pragma unroll
            for (int c = 0; c < 4; c++) wv[c] = w4[k * 64 + c2base + c];
            unsigned long long x2[4];
            #pragma unroll
            for (int j = 0; j < 4; j++) {
                float xe = (kk == 0) ? xv[j].x : (kk == 1) ? xv[j].y
                         : (kk == 2) ? xv[j].z : xv[j].w;
                x2[j] = pack2(xe);
            }
            #pragma unroll
            for (int j = 0; j < 4; j++)
                #pragma unroll
                for (int c = 0; c < 4; c++) {
                    fma2(accp[j][c], wv[c].x, x2[j]);
                    fma2(accn[j][c], wv[c].y, x2[j]);
                }
        }
    }

    // bias for my 8 columns
    const int colbase = 8 * tx;
    float4 bpA = *(const float4*)&b1p[colbase];
    float4 bpB = *(const float4*)&b1p[colbase + 4];
    float4 bnA = *(const float4*)&b1n[colbase];
    float4 bnB = *(const float4*)&b1n[colbase + 4];

    #pragma unroll
    for (int j = 0; j < 4; j++) {
        int row = base + 4 * ty + j;
        if (row >= n) continue;
        float dp = g_dinvp[row], dn = g_dinvn[row];
        float p[8], q[8];
        #pragma unroll
        for (int c = 0; c < 4; c++) {
            unpack2(accp[j][c], p[2 * c], p[2 * c + 1]);
            unpack2(accn[j][c], q[2 * c], q[2 * c + 1]);
        }
        float* hp = g_hps + row * H_ + colbase;
        float* hn = g_hns + row * H_ + colbase;
        float* hh = g_h   + row * H_ + colbase;
        float4 v;
        v = make_float4(p[0]*dp, p[1]*dp, p[2]*dp, p[3]*dp); *(float4*)hp = v;
        v = make_float4(p[4]*dp, p[5]*dp, p[6]*dp, p[7]*dp); *(float4*)(hp+4) = v;
        v = make_float4(q[0]*dn, q[1]*dn, q[2]*dn, q[3]*dn); *(float4*)hn = v;
        v = make_float4(q[4]*dn, q[5]*dn, q[6]*dn, q[7]*dn); *(float4*)(hn+4) = v;
        float dp2 = dp * dp, dn2 = dn * dn;
        v = make_float4(p[0]*dp2 + bpA.x - q[0]*dn2 - bnA.x,
                        p[1]*dp2 + bpA.y - q[1]*dn2 - bnA.y,
                        p[2]*dp2 + bpA.z - q[2]*dn2 - bnA.z,
                        p[3]*dp2 + bpA.w - q[3]*dn2 - bnA.w);
        *(float4*)hh = v;
        v = make_float4(p[4]*dp2 + bpB.x - q[4]*dn2 - bnB.x,
                        p[5]*dp2 + bpB.y - q[5]*dn2 - bnB.y,
                        p[6]*dp2 + bpB.z - q[6]*dn2 - bnB.z,
                        p[7]*dp2 + bpB.w - q[7]*dn2 - bnB.w);
        *(float4*)(hh + 4) = v;
    }
}

// ---------------- edge aggregation layer 1 (warp per edge, F=128) --------------
__global__ __launch_bounds__(256) void k_edge1(const int* __restrict__ ei,
                                               const float* __restrict__ w, int E)
{
    int wid = (blockIdx.x * blockDim.x + threadIdx.x) >> 5;
    if (wid >= E) return;
    int lane = threadIdx.x & 31;
    int s = __ldg(ei + wid);
    int t = __ldg(ei + E + wid);
    float we = __ldg(w + wid);
    const float* src;
    float scale;
    if (we >= 0.f) { src = g_hps; scale = we * g_dinvp[t]; }
    else           { src = g_hns; scale = we * g_dinvn[t]; }
    float4 v = __ldg((const float4*)(src + s * H_) + lane);
    red_add_v4(g_h + t * H_ + lane * 4,
               v.x * scale, v.y * scale, v.z * scale, v.w * scale);
}

// ================ GEMM layer 2: relu(h)[N,128] -> (gps,gns,out)[N,64] ==========
// 256 threads: tx = tid&7 -> 8 output cols (4 col-pairs), ty = tid>>3 -> 2 rows.
#define SMEM2 (128 * 32 * 16 + 64 * H_ * 4)   // 64KB w4 + 32KB x = 96KB
__global__ __launch_bounds__(256, 2) void k_gemm2(
    const float* __restrict__ W2p, const float* __restrict__ b2p,
    const float* __restrict__ W2n, const float* __restrict__ b2n,
    float* __restrict__ out, int n)
{
    extern __shared__ char sm[];
    ulonglong2* w4 = (ulonglong2*)sm;                 // [128 k][32 c2]
    float* xs = (float*)(sm + 128 * 32 * 16);         // [64 row][128 k]
    const int tid = threadIdx.x;
    const int tx = tid & 7;           // cols 8*tx .. 8*tx+7
    const int ty = tid >> 3;          // rows 2*ty .. 2*ty+1
    const int c2base = tx * 4;
    const int base = blockIdx.x * 64;

    for (int i = tid; i < 128 * 32; i += 256) {
        int k  = i >> 5;
        int c2 = i & 31;
        union { float4 f; ulonglong2 u; } cv;
        cv.f = make_float4(W2p[(2 * c2) * H_ + k], W2p[(2 * c2 + 1) * H_ + k],
                           W2n[(2 * c2) * H_ + k], W2n[(2 * c2 + 1) * H_ + k]);
        w4[k * 32 + c2] = cv.u;
    }
    // x tile = relu(g_h), row-major [64][128]
    for (int i = tid; i < 64 * (H_ / 4); i += 256) {
        int r = i >> 5;
        int row = base + r;
        float4 v = make_float4(0.f, 0.f, 0.f, 0.f);
        if (row < n) {
            v = ((const float4*)g_h)[row * (H_ / 4) + (i & 31)];
            v.x = fmaxf(v.x, 0.f); v.y = fmaxf(v.y, 0.f);
            v.z = fmaxf(v.z, 0.f); v.w = fmaxf(v.w, 0.f);
        }
        ((float4*)xs)[i] = v;
    }
    __syncthreads();

    unsigned long long accp[2][4], accn[2][4];
    #pragma unroll
    for (int j = 0; j < 2; j++)
        #pragma unroll
        for (int c = 0; c < 4; c++) { accp[j][c] = 0ull; accn[j][c] = 0ull; }

    const float* xrow = xs + (2 * ty) * H_;
    for (int k4 = 0; k4 < H_ / 4; k4++) {
        float4 xv[2];
        #pragma unroll
        for (int j = 0; j < 2; j++)
            xv[j] = *(const float4*)&xrow[j * H_ + 4 * k4];
        #pragma unroll
        for (int kk = 0; kk < 4; kk++) {
            int k = 4 * k4 + kk;
            ulonglong2 wv[4];
            #pragma unroll
            for (int c = 0; c < 4; c++) wv[c] = w4[k * 32 + c2base + c];
            unsigned long long x2[2];
            #pragma unroll
            for (int j = 0; j < 2; j++) {
                float xe = (kk == 0) ? xv[j].x : (kk == 1) ? xv[j].y
                         : (kk == 2) ? xv[j].z : xv[j].w;
                x2[j] = pack2(xe);
            }
            #pragma unroll
            for (int j = 0; j < 2; j++)
                #pragma unroll
                for (int c = 0; c < 4; c++) {
                    fma2(accp[j][c], wv[c].x, x2[j]);
                    fma2(accn[j][c], wv[c].y, x2[j]);
                }
        }
    }

    const int colbase = 8 * tx;
    float4 bpA = *(const float4*)&b2p[colbase];
    float4 bpB = *(const float4*)&b2p[colbase + 4];
    float4 bnA = *(const float4*)&b2n[colbase];
    float4 bnB = *(const float4*)&b2n[colbase + 4];

    #pragma unroll
    for (int j = 0; j < 2; j++) {
        int row = base + 2 * ty + j;
        if (row >= n) continue;
        float dp = g_dinvp[row], dn = g_dinvn[row];
        float p[8], q[8];
        #pragma unroll
        for (int c = 0; c < 4; c++) {
            unpack2(accp[j][c], p[2 * c], p[2 * c + 1]);
            unpack2(accn[j][c], q[2 * c], q[2 * c + 1]);
        }
        float* gp = g_gps + row * O_ + colbase;
        float* gn = g_gns + row * O_ + colbase;
        float* oo = out   + row * O_ + colbase;
        float4 v;
        v = make_float4(p[0]*dp, p[1]*dp, p[2]*dp, p[3]*dp); *(float4*)gp = v;
        v = make_float4(p[4]*dp, p[5]*dp, p[6]*dp, p[7]*dp); *(float4*)(gp+4) = v;
        v = make_float4(q[0]*dn, q[1]*dn, q[2]*dn, q[3]*dn); *(float4*)gn = v;
        v = make_float4(q[4]*dn, q[5]*dn, q[6]*dn, q[7]*dn); *(float4*)(gn+4) = v;
        float dp2 = dp * dp, dn2 = dn * dn;
        v = make_float4(p[0]*dp2 + bpA.x - q[0]*dn2 - bnA.x,
                        p[1]*dp2 + bpA.y - q[1]*dn2 - bnA.y,
                        p[2]*dp2 + bpA.z - q[2]*dn2 - bnA.z,
                        p[3]*dp2 + bpA.w - q[3]*dn2 - bnA.w);
        *(float4*)oo = v;
        v = make_float4(p[4]*dp2 + bpB.x - q[4]*dn2 - bnB.x,
                        p[5]*dp2 + bpB.y - q[5]*dn2 - bnB.y,
                        p[6]*dp2 + bpB.z - q[6]*dn2 - bnB.z,
                        p[7]*dp2 + bpB.w - q[7]*dn2 - bnB.w);
        *(float4*)(oo + 4) = v;
    }
}

// ---------------- edge aggregation layer 2 (16 lanes per edge, F=64) -----------
__global__ __launch_bounds__(256) void k_edge2(const int* __restrict__ ei,
                                               const float* __restrict__ w,
                                               float* __restrict__ out, int E)
{
    int gid = blockIdx.x * blockDim.x + threadIdx.x;
    int e = gid >> 4;
    if (e >= E) return;
    int sub = gid & 15;
    int s = __ldg(ei + e);
    int t = __ldg(ei + E + e);
    float we = __ldg(w + e);
    const float* src;
    float scale;
    if (we >= 0.f) { src = g_gps; scale = we * g_dinvp[t]; }
    else           { src = g_gns; scale = we * g_dinvn[t]; }
    float4 v = __ldg((const float4*)(src + s * O_) + sub);
    red_add_v4(out + t * O_ + sub * 4,
               v.x * scale, v.y * scale, v.z * scale, v.w * scale);
}

__global__ void k_relu_out(float* __restrict__ out, int n4) {
    int i = blockIdx.x * blockDim.x + threadIdx.x;
    if (i >= n4) return;
    float4 v = ((float4*)out)[i];
    v.x = fmaxf(v.x, 0.f); v.y = fmaxf(v.y, 0.f);
    v.z = fmaxf(v.z, 0.f); v.w = fmaxf(v.w, 0.f);
    ((float4*)out)[i] = v;
}

// ---------------- launch --------------------------------------------------------
extern "C" void kernel_launch(void* const* d_in, const int* in_sizes, int n_in,
                              void* d_out, int out_size)
{
    const float* x   = (const float*)d_in[0];
    const int*   ei  = (const int*)  d_in[1];
    const float* w   = (const float*)d_in[2];
    const float* W1p = (const float*)d_in[3];
    const float* b1p = (const float*)d_in[4];
    const float* W1n = (const float*)d_in[5];
    const float* b1n = (const float*)d_in[6];
    const float* W2p = (const float*)d_in[7];
    const float* b2p = (const float*)d_in[8];
    const float* W2n = (const float*)d_in[9];
    const float* b2n = (const float*)d_in[10];
    float* out = (float*)d_out;

    const int n = in_sizes[0] / IN_;
    const int E = in_sizes[2];

    cudaFuncSetAttribute(k_gemm1, cudaFuncAttributeMaxDynamicSharedMemorySize, SMEM1);
    cudaFuncSetAttribute(k_gemm2, cudaFuncAttributeMaxDynamicSharedMemorySize, SMEM2);

    k_zero_deg<<<(n + 255) / 256, 256>>>(n);
    k_deg<<<(E + 255) / 256, 256>>>(ei, w, E);
    k_dinv<<<(n + 255) / 256, 256>>>(n);

    k_gemm1<<<(n + 63) / 64, 256, SMEM1>>>(x, W1p, b1p, W1n, b1n, n);
    k_edge1<<<(E + 7) / 8, 256>>>(ei, w, E);

    k_gemm2<<<(n + 63) / 64, 256, SMEM2>>>(W2p, b2p, W2n, b2n, out, n);
    k_edge2<<<(E * 16 + 255) / 256, 256>>>(ei, w, out, E);
    k_relu_out<<<(n * O_ / 4 + 255) / 256, 256>>>(out, n * O_ / 4);
}

// round 4
// speedup vs baseline: 1.7327x; 1.7327x over previous
#include <cuda_runtime.h>
#include <cuda_bf16.h>

#define N_   100000
#define E_   1600000
#define IN_  64
#define H_   128
#define O_   64

// ---------------- scratch -------------------------------------------------------
__device__ float g_degp[N_];
__device__ float g_degn[N_];
__device__ float g_dinvp[N_];
__device__ float g_dinvn[N_];
__device__ float g_hps[N_ * H_];
__device__ float g_hns[N_ * H_];
__device__ float g_h  [N_ * H_];
__device__ float g_gps[N_ * O_];
__device__ float g_gns[N_ * O_];

// ---------------- helpers ------------------------------------------------------
__device__ __forceinline__ void red_add_v4(float* p, float a, float b, float c, float d) {
    asm volatile("red.global.add.v4.f32 [%0], {%1,%2,%3,%4};"
                 :: "l"(p), "f"(a), "f"(b), "f"(c), "f"(d) : "memory");
}

__device__ __forceinline__ void fma2(unsigned long long& acc,
                                     unsigned long long w,
                                     unsigned long long xx) {
    asm("fma.rn.f32x2 %0, %1, %2, %0;" : "+l"(acc) : "l"(w), "l"(xx));
}

__device__ __forceinline__ unsigned long long packf2(float a, float b) {
    unsigned long long r;
    asm("mov.b64 %0, {%1, %2};" : "=l"(r) : "f"(a), "f"(b));
    return r;
}

__device__ __forceinline__ void unpack2(unsigned long long v, float& lo, float& hi) {
    asm("mov.b64 {%0, %1}, %2;" : "=f"(lo), "=f"(hi) : "l"(v));
}

// ---------------- degree / dinv -------------------------------------------------
__global__ void k_zero_deg(int n) {
    int i = blockIdx.x * blockDim.x + threadIdx.x;
    if (i < n) { g_degp[i] = 0.f; g_degn[i] = 0.f; }
}

__global__ void k_deg(const int* __restrict__ ei, const float* __restrict__ w, int E) {
    int e = blockIdx.x * blockDim.x + threadIdx.x;
    if (e >= E) return;
    float we = w[e];
    int t = ei[E + e];
    if (we > 0.f)      atomicAdd(&g_degp[t], we);
    else if (we < 0.f) atomicAdd(&g_degn[t], -we);
}

__global__ void k_dinv(int n) {
    int i = blockIdx.x * blockDim.x + threadIdx.x;
    if (i < n) {
        g_dinvp[i] = rsqrtf(g_degp[i] + 1.0f);
        g_dinvn[i] = rsqrtf(g_degn[i] + 1.0f);
    }
}

// ================ GEMM layer 1: x[N,64] -> (hps,hns,h)[N,128] ====================
// CTA tile 64 rows x 64 cols. 128 threads: tx=tid&63 (col), ty=tid>>6 (row half).
// k-pair packed f32x2: acc2 += (w[k],w[k+1]) * (x[k],x[k+1]); final = lo+hi.
// smem: ws[k2][c] = ulonglong2(wp_pair, wn_pair), c bank-swizzled by (k2&15);
//       xs[row][k] natural row-major (reads are warp-broadcast).
#define SMEM1 (32 * 64 * 16 + 64 * 64 * 4 + 2 * 64 * 4)   // 49664 B
__global__ __launch_bounds__(128) void k_gemm1(
    const float* __restrict__ x,
    const float* __restrict__ W1p, const float* __restrict__ b1p,
    const float* __restrict__ W1n, const float* __restrict__ b1n, int n)
{
    extern __shared__ char sm[];
    ulonglong2* ws = (ulonglong2*)sm;                       // [32 k2][64 c]
    float* xs  = (float*)(sm + 32 * 64 * 16);               // [64 r][64 k]
    float* sdp = (float*)(sm + 32 * 64 * 16 + 64 * 64 * 4); // [64]
    float* sdn = sdp + 64;

    const int tid = threadIdx.x;
    const int tx = tid & 63;
    const int ty = tid >> 6;
    const int rowBlocks = gridDim.x >> 1;
    const int rb  = blockIdx.x >> 1;
    const int colbase = (blockIdx.x & 1) * 64;
    const int base = rb * 64;
    (void)rowBlocks;

    // weights -> smem (coalesced along k), swizzled STS
    for (int i = tid; i < 16 * 64; i += 128) {
        int k4 = i & 15;
        int c  = i >> 4;
        int col = colbase + c;
        float4 wp = *(const float4*)&W1p[col * IN_ + 4 * k4];
        float4 wn = *(const float4*)&W1n[col * IN_ + 4 * k4];
        int k2a = 2 * k4, k2b = 2 * k4 + 1;
        ws[k2a * 64 + (c ^ (k2a & 15))] =
            make_ulonglong2(packf2(wp.x, wp.y), packf2(wn.x, wn.y));
        ws[k2b * 64 + (c ^ (k2b & 15))] =
            make_ulonglong2(packf2(wp.z, wp.w), packf2(wn.z, wn.w));
    }
    // x tile (natural layout, fully coalesced)
    for (int i = tid; i < 64 * 16; i += 128) {
        int r = i >> 4;
        int row = base + r;
        float4 v = make_float4(0.f, 0.f, 0.f, 0.f);
        if (row < n) v = ((const float4*)x)[row * 16 + (i & 15)];
        ((float4*)xs)[i] = v;
    }
    if (tid < 64) {
        int row = base + tid;
        sdp[tid] = (row < n) ? g_dinvp[row] : 0.f;
        sdn[tid] = (row < n) ? g_dinvn[row] : 0.f;
    }
    __syncthreads();

    const int col = colbase + tx;
    const float bp = b1p[col], bn = b1n[col];

    for (int chunk = 0; chunk < 4; chunk++) {
        const int rbase = ty * 32 + chunk * 8;
        unsigned long long accp[8], accn[8];
        #pragma unroll
        for (int r = 0; r < 8; r++) { accp[r] = 0ull; accn[r] = 0ull; }

        #pragma unroll 4
        for (int k4 = 0; k4 < 16; k4++) {
            int k2a = 2 * k4, k2b = 2 * k4 + 1;
            ulonglong2 w0 = ws[k2a * 64 + (tx ^ (k2a & 15))];
            ulonglong2 w1 = ws[k2b * 64 + (tx ^ (k2b & 15))];
            #pragma unroll
            for (int r = 0; r < 8; r++) {
                float4 xv = *(const float4*)&xs[(rbase + r) * 64 + 4 * k4];
                unsigned long long x0 = packf2(xv.x, xv.y);
                unsigned long long x1 = packf2(xv.z, xv.w);
                fma2(accp[r], w0.x, x0);
                fma2(accn[r], w0.y, x0);
                fma2(accp[r], w1.x, x1);
                fma2(accn[r], w1.y, x1);
            }
        }

        #pragma unroll
        for (int r = 0; r < 8; r++) {
            int rr = rbase + r;
            int row = base + rr;
            if (row >= n) continue;
            float pl, ph, ql, qh;
            unpack2(accp[r], pl, ph);
            unpack2(accn[r], ql, qh);
            float ap = pl + ph, an = ql + qh;
            float dp = sdp[rr], dn = sdn[rr];
            g_hps[row * H_ + col] = ap * dp;
            g_hns[row * H_ + col] = an * dn;
            g_h  [row * H_ + col] = ap * dp * dp + bp - an * dn * dn - bn;
        }
    }
}

// ---------------- edge aggregation layer 1 (warp per edge, F=128) ---------------
__global__ __launch_bounds__(256) void k_edge1(const int* __restrict__ ei,
                                               const float* __restrict__ w, int E)
{
    int wid = (blockIdx.x * blockDim.x + threadIdx.x) >> 5;
    if (wid >= E) return;
    int lane = threadIdx.x & 31;
    int s = __ldg(ei + wid);
    int t = __ldg(ei + E + wid);
    float we = __ldg(w + wid);
    const float* src;
    float scale;
    if (we >= 0.f) { src = g_hps; scale = we * g_dinvp[t]; }
    else           { src = g_hns; scale = we * g_dinvn[t]; }
    float4 v = __ldg((const float4*)(src + s * H_) + lane);
    red_add_v4(g_h + t * H_ + lane * 4,
               v.x * scale, v.y * scale, v.z * scale, v.w * scale);
}

// ================ GEMM layer 2: relu(h)[N,128] -> (gps,gns,out)[N,64] ============
#define SMEM2 (64 * 64 * 16 + 64 * 128 * 4 + 2 * 64 * 4)   // 98816 B
__global__ __launch_bounds__(128) void k_gemm2(
    const float* __restrict__ W2p, const float* __restrict__ b2p,
    const float* __restrict__ W2n, const float* __restrict__ b2n,
    float* __restrict__ out, int n)
{
    extern __shared__ char sm[];
    ulonglong2* ws = (ulonglong2*)sm;                        // [64 k2][64 c]
    float* xs  = (float*)(sm + 64 * 64 * 16);                // [64 r][128 k]
    float* sdp = (float*)(sm + 64 * 64 * 16 + 64 * 128 * 4); // [64]
    float* sdn = sdp + 64;

    const int tid = threadIdx.x;
    const int tx = tid & 63;
    const int ty = tid >> 6;
    const int base = blockIdx.x * 64;

    for (int i = tid; i < 32 * 64; i += 128) {
        int k4 = i & 31;
        int c  = i >> 5;
        float4 wp = *(const float4*)&W2p[c * H_ + 4 * k4];
        float4 wn = *(const float4*)&W2n[c * H_ + 4 * k4];
        int k2a = 2 * k4, k2b = 2 * k4 + 1;
        ws[k2a * 64 + (c ^ (k2a & 15))] =
            make_ulonglong2(packf2(wp.x, wp.y), packf2(wn.x, wn.y));
        ws[k2b * 64 + (c ^ (k2b & 15))] =
            make_ulonglong2(packf2(wp.z, wp.w), packf2(wn.z, wn.w));
    }
    // x tile = relu(g_h)
    for (int i = tid; i < 64 * 32; i += 128) {
        int r = i >> 5;
        int row = base + r;
        float4 v = make_float4(0.f, 0.f, 0.f, 0.f);
        if (row < n) {
            v = ((const float4*)g_h)[row * 32 + (i & 31)];
            v.x = fmaxf(v.x, 0.f); v.y = fmaxf(v.y, 0.f);
            v.z = fmaxf(v.z, 0.f); v.w = fmaxf(v.w, 0.f);
        }
        ((float4*)xs)[i] = v;
    }
    if (tid < 64) {
        int row = base + tid;
        sdp[tid] = (row < n) ? g_dinvp[row] : 0.f;
        sdn[tid] = (row < n) ? g_dinvn[row] : 0.f;
    }
    __syncthreads();

    const float bp = b2p[tx], bn = b2n[tx];

    for (int chunk = 0; chunk < 4; chunk++) {
        const int rbase = ty * 32 + chunk * 8;
        unsigned long long accp[8], accn[8];
        #pragma unroll
        for (int r = 0; r < 8; r++) { accp[r] = 0ull; accn[r] = 0ull; }

        #pragma unroll 4
        for (int k4 = 0; k4 < 32; k4++) {
            int k2a = 2 * k4, k2b = 2 * k4 + 1;
            ulonglong2 w0 = ws[k2a * 64 + (tx ^ (k2a & 15))];
            ulonglong2 w1 = ws[k2b * 64 + (tx ^ (k2b & 15))];
            #pragma unroll
            for (int r = 0; r < 8; r++) {
                float4 xv = *(const float4*)&xs[(rbase + r) * 128 + 4 * k4];
                unsigned long long x0 = packf2(xv.x, xv.y);
                unsigned long long x1 = packf2(xv.z, xv.w);
                fma2(accp[r], w0.x, x0);
                fma2(accn[r], w0.y, x0);
                fma2(accp[r], w1.x, x1);
                fma2(accn[r], w1.y, x1);
            }
        }

        #pragma unroll
        for (int r = 0; r < 8; r++) {
            int rr = rbase + r;
            int row = base + rr;
            if (row >= n) continue;
            float pl, ph, ql, qh;
            unpack2(accp[r], pl, ph);
            unpack2(accn[r], ql, qh);
            float ap = pl + ph, an = ql + qh;
            float dp = sdp[rr], dn = sdn[rr];
            g_gps[row * O_ + tx] = ap * dp;
            g_gns[row * O_ + tx] = an * dn;
            out  [row * O_ + tx] = ap * dp * dp + bp - an * dn * dn - bn;
        }
    }
}

// ---------------- edge aggregation layer 2 (16 lanes per edge, F=64) ------------
__global__ __launch_bounds__(256) void k_edge2(const int* __restrict__ ei,
                                               const float* __restrict__ w,
                                               float* __restrict__ out, int E)
{
    int gid = blockIdx.x * blockDim.x + threadIdx.x;
    int e = gid >> 4;
    if (e >= E) return;
    int sub = gid & 15;
    int s = __ldg(ei + e);
    int t = __ldg(ei + E + e);
    float we = __ldg(w + e);
    const float* src;
    float scale;
    if (we >= 0.f) { src = g_gps; scale = we * g_dinvp[t]; }
    else           { src = g_gns; scale = we * g_dinvn[t]; }
    float4 v = __ldg((const float4*)(src + s * O_) + sub);
    red_add_v4(out + t * O_ + sub * 4,
               v.x * scale, v.y * scale, v.z * scale, v.w * scale);
}

__global__ void k_relu_out(float* __restrict__ out, int n4) {
    int i = blockIdx.x * blockDim.x + threadIdx.x;
    if (i >= n4) return;
    float4 v = ((float4*)out)[i];
    v.x = fmaxf(v.x, 0.f); v.y = fmaxf(v.y, 0.f);
    v.z = fmaxf(v.z, 0.f); v.w = fmaxf(v.w, 0.f);
    ((float4*)out)[i] = v;
}

// ---------------- launch ---------------------------------------------------------
extern "C" void kernel_launch(void* const* d_in, const int* in_sizes, int n_in,
                              void* d_out, int out_size)
{
    const float* x   = (const float*)d_in[0];
    const int*   ei  = (const int*)  d_in[1];
    const float* w   = (const float*)d_in[2];
    const float* W1p = (const float*)d_in[3];
    const float* b1p = (const float*)d_in[4];
    const float* W1n = (const float*)d_in[5];
    const float* b1n = (const float*)d_in[6];
    const float* W2p = (const float*)d_in[7];
    const float* b2p = (const float*)d_in[8];
    const float* W2n = (const float*)d_in[9];
    const float* b2n = (const float*)d_in[10];
    float* out = (float*)d_out;

    const int n = in_sizes[0] / IN_;
    const int E = in_sizes[2];
    const int rowBlocks = (n + 63) / 64;

    cudaFuncSetAttribute(k_gemm1, cudaFuncAttributeMaxDynamicSharedMemorySize, SMEM1);
    cudaFuncSetAttribute(k_gemm2, cudaFuncAttributeMaxDynamicSharedMemorySize, SMEM2);

    k_zero_deg<<<(n + 255) / 256, 256>>>(n);
    k_deg<<<(E + 255) / 256, 256>>>(ei, w, E);
    k_dinv<<<(n + 255) / 256, 256>>>(n);

    k_gemm1<<<rowBlocks * 2, 128, SMEM1>>>(x, W1p, b1p, W1n, b1n, n);
    k_edge1<<<(E + 7) / 8, 256>>>(ei, w, E);

    k_gemm2<<<rowBlocks, 128, SMEM2>>>(W2p, b2p, W2n, b2n, out, n);
    k_edge2<<<(E * 16 + 255) / 256, 256>>>(ei, w, out, E);
    k_relu_out<<<(n * O_ / 4 + 255) / 256, 256>>>(out, n * O_ / 4);
}

// round 5
// speedup vs baseline: 1.7511x; 1.0106x over previous
#include <cuda_runtime.h>
#include <cuda_bf16.h>

#define N_   100000
#define E_   1600000
#define IN_  64
#define H_   128
#define O_   64

// ---------------- scratch -------------------------------------------------------
__device__ float g_degp[N_];
__device__ float g_degn[N_];
__device__ float g_dinvp[N_];
__device__ float g_dinvn[N_];
__device__ float g_hps[N_ * H_];
__device__ float g_hns[N_ * H_];
__device__ float g_h  [N_ * H_];
__device__ float g_gps[N_ * O_];
__device__ float g_gns[N_ * O_];

// ---------------- helpers ------------------------------------------------------
__device__ __forceinline__ void red_add_v4(float* p, float a, float b, float c, float d) {
    asm volatile("red.global.add.v4.f32 [%0], {%1,%2,%3,%4};"
                 :: "l"(p), "f"(a), "f"(b), "f"(c), "f"(d) : "memory");
}

__device__ __forceinline__ void fma2(unsigned long long& acc,
                                     unsigned long long w,
                                     unsigned long long xx) {
    asm("fma.rn.f32x2 %0, %1, %2, %0;" : "+l"(acc) : "l"(w), "l"(xx));
}

__device__ __forceinline__ unsigned long long packf2(float a, float b) {
    unsigned long long r;
    asm("mov.b64 %0, {%1, %2};" : "=l"(r) : "f"(a), "f"(b));
    return r;
}

__device__ __forceinline__ void unpack2(unsigned long long v, float& lo, float& hi) {
    asm("mov.b64 {%0, %1}, %2;" : "=f"(lo), "=f"(hi) : "l"(v));
}

// ---------------- degree / dinv -------------------------------------------------
__global__ void k_zero_deg(int n) {
    int i = blockIdx.x * blockDim.x + threadIdx.x;
    if (i < n) { g_degp[i] = 0.f; g_degn[i] = 0.f; }
}

__global__ void k_deg(const int* __restrict__ ei, const float* __restrict__ w, int E) {
    int e = blockIdx.x * blockDim.x + threadIdx.x;
    if (e >= E) return;
    float we = w[e];
    int t = ei[E + e];
    if (we > 0.f)      atomicAdd(&g_degp[t], we);
    else if (we < 0.f) atomicAdd(&g_degn[t], -we);
}

__global__ void k_dinv(int n) {
    int i = blockIdx.x * blockDim.x + threadIdx.x;
    if (i < n) {
        g_dinvp[i] = rsqrtf(g_degp[i] + 1.0f);
        g_dinvn[i] = rsqrtf(g_degn[i] + 1.0f);
    }
}

// ================ GEMM layer 1: x[N,64] -> (hps,hns,h)[N,128] ====================
// CTA tile 64 rows x 64 cols. 128 threads: tx=tid&63 (col), ty=tid>>6 (row half).
// k-pair packed f32x2. k-loop FULLY unrolled -> all smem addresses are immediates.
#define SMEM1 (32 * 64 * 16 + 64 * 64 * 4 + 2 * 64 * 4)   // 49664 B
__global__ __launch_bounds__(128) void k_gemm1(
    const float* __restrict__ x,
    const float* __restrict__ W1p, const float* __restrict__ b1p,
    const float* __restrict__ W1n, const float* __restrict__ b1n, int n)
{
    extern __shared__ char sm[];
    ulonglong2* ws = (ulonglong2*)sm;                       // [32 k2][64 c]
    float* xs  = (float*)(sm + 32 * 64 * 16);               // [64 r][64 k]
    float* sdp = (float*)(sm + 32 * 64 * 16 + 64 * 64 * 4); // [64]
    float* sdn = sdp + 64;

    const int tid = threadIdx.x;
    const int tx = tid & 63;
    const int ty = tid >> 6;
    const int rb  = blockIdx.x >> 1;
    const int colbase = (blockIdx.x & 1) * 64;
    const int base = rb * 64;

    for (int i = tid; i < 16 * 64; i += 128) {
        int k4 = i & 15;
        int c  = i >> 4;
        int col = colbase + c;
        float4 wp = *(const float4*)&W1p[col * IN_ + 4 * k4];
        float4 wn = *(const float4*)&W1n[col * IN_ + 4 * k4];
        int k2a = 2 * k4, k2b = 2 * k4 + 1;
        ws[k2a * 64 + (c ^ (k2a & 15))] =
            make_ulonglong2(packf2(wp.x, wp.y), packf2(wn.x, wn.y));
        ws[k2b * 64 + (c ^ (k2b & 15))] =
            make_ulonglong2(packf2(wp.z, wp.w), packf2(wn.z, wn.w));
    }
    for (int i = tid; i < 64 * 16; i += 128) {
        int r = i >> 4;
        int row = base + r;
        float4 v = make_float4(0.f, 0.f, 0.f, 0.f);
        if (row < n) v = ((const float4*)x)[row * 16 + (i & 15)];
        ((float4*)xs)[i] = v;
    }
    if (tid < 64) {
        int row = base + tid;
        sdp[tid] = (row < n) ? g_dinvp[row] : 0.f;
        sdn[tid] = (row < n) ? g_dinvn[row] : 0.f;
    }
    __syncthreads();

    const int col = colbase + tx;
    const float bp = b1p[col], bn = b1n[col];

    for (int chunk = 0; chunk < 4; chunk++) {
        const int rbase = ty * 32 + chunk * 8;
        const float* xrow = xs + rbase * 64;
        unsigned long long accp[8], accn[8];
        #pragma unroll
        for (int r = 0; r < 8; r++) { accp[r] = 0ull; accn[r] = 0ull; }

        #pragma unroll
        for (int k4 = 0; k4 < 16; k4++) {
            const int k2a = 2 * k4, k2b = 2 * k4 + 1;
            ulonglong2 w0 = ws[k2a * 64 + (tx ^ (k2a & 15))];
            ulonglong2 w1 = ws[k2b * 64 + (tx ^ (k2b & 15))];
            #pragma unroll
            for (int r = 0; r < 8; r++) {
                float4 xv = *(const float4*)&xrow[r * 64 + 4 * k4];
                unsigned long long x0 = packf2(xv.x, xv.y);
                unsigned long long x1 = packf2(xv.z, xv.w);
                fma2(accp[r], w0.x, x0);
                fma2(accn[r], w0.y, x0);
                fma2(accp[r], w1.x, x1);
                fma2(accn[r], w1.y, x1);
            }
        }

        #pragma unroll
        for (int r = 0; r < 8; r++) {
            int rr = rbase + r;
            int row = base + rr;
            if (row >= n) continue;
            float pl, ph, ql, qh;
            unpack2(accp[r], pl, ph);
            unpack2(accn[r], ql, qh);
            float ap = pl + ph, an = ql + qh;
            float dp = sdp[rr], dn = sdn[rr];
            g_hps[row * H_ + col] = ap * dp;
            g_hns[row * H_ + col] = an * dn;
            g_h  [row * H_ + col] = ap * dp * dp + bp - an * dn * dn - bn;
        }
    }
}

// ---------------- edge aggregation layer 1 (warp per edge, F=128) ---------------
__global__ __launch_bounds__(256) void k_edge1(const int* __restrict__ ei,
                                               const float* __restrict__ w, int E)
{
    int wid = (blockIdx.x * blockDim.x + threadIdx.x) >> 5;
    if (wid >= E) return;
    int lane = threadIdx.x & 31;
    int s = __ldg(ei + wid);
    int t = __ldg(ei + E + wid);
    float we = __ldg(w + wid);
    const float* src;
    float scale;
    if (we >= 0.f) { src = g_hps; scale = we * g_dinvp[t]; }
    else           { src = g_hns; scale = we * g_dinvn[t]; }
    float4 v = __ldg((const float4*)(src + s * H_) + lane);
    red_add_v4(g_h + t * H_ + lane * 4,
               v.x * scale, v.y * scale, v.z * scale, v.w * scale);
}

// ================ GEMM layer 2: relu(h)[N,128] -> (gps,gns,out)[N,64] ============
#define SMEM2 (64 * 64 * 16 + 64 * 128 * 4 + 2 * 64 * 4)   // 98816 B
__global__ __launch_bounds__(128) void k_gemm2(
    const float* __restrict__ W2p, const float* __restrict__ b2p,
    const float* __restrict__ W2n, const float* __restrict__ b2n,
    float* __restrict__ out, int n)
{
    extern __shared__ char sm[];
    ulonglong2* ws = (ulonglong2*)sm;                        // [64 k2][64 c]
    float* xs  = (float*)(sm + 64 * 64 * 16);                // [64 r][128 k]
    float* sdp = (float*)(sm + 64 * 64 * 16 + 64 * 128 * 4); // [64]
    float* sdn = sdp + 64;

    const int tid = threadIdx.x;
    const int tx = tid & 63;
    const int ty = tid >> 6;
    const int base = blockIdx.x * 64;

    for (int i = tid; i < 32 * 64; i += 128) {
        int k4 = i & 31;
        int c  = i >> 5;
        float4 wp = *(const float4*)&W2p[c * H_ + 4 * k4];
        float4 wn = *(const float4*)&W2n[c * H_ + 4 * k4];
        int k2a = 2 * k4, k2b = 2 * k4 + 1;
        ws[k2a * 64 + (c ^ (k2a & 15))] =
            make_ulonglong2(packf2(wp.x, wp.y), packf2(wn.x, wn.y));
        ws[k2b * 64 + (c ^ (k2b & 15))] =
            make_ulonglong2(packf2(wp.z, wp.w), packf2(wn.z, wn.w));
    }
    for (int i = tid; i < 64 * 32; i += 128) {
        int r = i >> 5;
        int row = base + r;
        float4 v = make_float4(0.f, 0.f, 0.f, 0.f);
        if (row < n) {
            v = ((const float4*)g_h)[row * 32 + (i & 31)];
            v.x = fmaxf(v.x, 0.f); v.y = fmaxf(v.y, 0.f);
            v.z = fmaxf(v.z, 0.f); v.w = fmaxf(v.w, 0.f);
        }
        ((float4*)xs)[i] = v;
    }
    if (tid < 64) {
        int row = base + tid;
        sdp[tid] = (row < n) ? g_dinvp[row] : 0.f;
        sdn[tid] = (row < n) ? g_dinvn[row] : 0.f;
    }
    __syncthreads();

    const float bp = b2p[tx], bn = b2n[tx];

    for (int chunk = 0; chunk < 4; chunk++) {
        const int rbase = ty * 32 + chunk * 8;
        const float* xrow = xs + rbase * 128;
        unsigned long long accp[8], accn[8];
        #pragma unroll
        for (int r = 0; r < 8; r++) { accp[r] = 0ull; accn[r] = 0ull; }

        #pragma unroll 8
        for (int k4 = 0; k4 < 32; k4++) {
            const int k2a = 2 * k4, k2b = 2 * k4 + 1;
            ulonglong2 w0 = ws[k2a * 64 + (tx ^ (k2a & 15))];
            ulonglong2 w1 = ws[k2b * 64 + (tx ^ (k2b & 15))];
            #pragma unroll
            for (int r = 0; r < 8; r++) {
                float4 xv = *(const float4*)&xrow[r * 128 + 4 * k4];
                unsigned long long x0 = packf2(xv.x, xv.y);
                unsigned long long x1 = packf2(xv.z, xv.w);
                fma2(accp[r], w0.x, x0);
                fma2(accn[r], w0.y, x0);
                fma2(accp[r], w1.x, x1);
                fma2(accn[r], w1.y, x1);
            }
        }

        #pragma unroll
        for (int r = 0; r < 8; r++) {
            int rr = rbase + r;
            int row = base + rr;
            if (row >= n) continue;
            float pl, ph, ql, qh;
            unpack2(accp[r], pl, ph);
            unpack2(accn[r], ql, qh);
            float ap = pl + ph, an = ql + qh;
            float dp = sdp[rr], dn = sdn[rr];
            g_gps[row * O_ + tx] = ap * dp;
            g_gns[row * O_ + tx] = an * dn;
            out  [row * O_ + tx] = ap * dp * dp + bp - an * dn * dn - bn;
        }
    }
}

// ---------------- edge aggregation layer 2 (16 lanes per edge, F=64) ------------
__global__ __launch_bounds__(256) void k_edge2(const int* __restrict__ ei,
                                               const float* __restrict__ w,
                                               float* __restrict__ out, int E)
{
    int gid = blockIdx.x * blockDim.x + threadIdx.x;
    int e = gid >> 4;
    if (e >= E) return;
    int sub = gid & 15;
    int s = __ldg(ei + e);
    int t = __ldg(ei + E + e);
    float we = __ldg(w + e);
    const float* src;
    float scale;
    if (we >= 0.f) { src = g_gps; scale = we * g_dinvp[t]; }
    else           { src = g_gns; scale = we * g_dinvn[t]; }
    float4 v = __ldg((const float4*)(src + s * O_) + sub);
    red_add_v4(out + t * O_ + sub * 4,
               v.x * scale, v.y * scale, v.z * scale, v.w * scale);
}

__global__ void k_relu_out(float* __restrict__ out, int n4) {
    int i = blockIdx.x * blockDim.x + threadIdx.x;
    if (i >= n4) return;
    float4 v = ((float4*)out)[i];
    v.x = fmaxf(v.x, 0.f); v.y = fmaxf(v.y, 0.f);
    v.z = fmaxf(v.z, 0.f); v.w = fmaxf(v.w, 0.f);
    ((float4*)out)[i] = v;
}

// ---------------- launch ---------------------------------------------------------
extern "C" void kernel_launch(void* const* d_in, const int* in_sizes, int n_in,
                              void* d_out, int out_size)
{
    const float* x   = (const float*)d_in[0];
    const int*   ei  = (const int*)  d_in[1];
    const float* w   = (const float*)d_in[2];
    const float* W1p = (const float*)d_in[3];
    const float* b1p = (const float*)d_in[4];
    const float* W1n = (const float*)d_in[5];
    const float* b1n = (const float*)d_in[6];
    const float* W2p = (const float*)d_in[7];
    const float* b2p = (const float*)d_in[8];
    const float* W2n = (const float*)d_in[9];
    const float* b2n = (const float*)d_in[10];
    float* out = (float*)d_out;

    const int n = in_sizes[0] / IN_;
    const int E = in_sizes[2];
    const int rowBlocks = (n + 63) / 64;

    cudaFuncSetAttribute(k_gemm1, cudaFuncAttributeMaxDynamicSharedMemorySize, SMEM1);
    cudaFuncSetAttribute(k_gemm2, cudaFuncAttributeMaxDynamicSharedMemorySize, SMEM2);

    k_zero_deg<<<(n + 255) / 256, 256>>>(n);
    k_deg<<<(E + 255) / 256, 256>>>(ei, w, E);
    k_dinv<<<(n + 255) / 256, 256>>>(n);

    k_gemm1<<<rowBlocks * 2, 128, SMEM1>>>(x, W1p, b1p, W1n, b1n, n);
    k_edge1<<<(E + 7) / 8, 256>>>(ei, w, E);

    k_gemm2<<<rowBlocks, 128, SMEM2>>>(W2p, b2p, W2n, b2n, out, n);
    k_edge2<<<(E * 16 + 255) / 256, 256>>>(ei, w, out, E);
    k_relu_out<<<(n * O_ / 4 + 255) / 256, 256>>>(out, n * O_ / 4);
}

// round 6
// speedup vs baseline: 1.8289x; 1.0444x over previous
#include <cuda_runtime.h>
#include <cuda_bf16.h>

#define N_   100000
#define E_   1600000
#define IN_  64
#define H_   128
#define O_   64

// ---------------- scratch -------------------------------------------------------
__device__ float g_degp[N_];
__device__ float g_degn[N_];
__device__ float g_dinvp[N_];
__device__ float g_dinvn[N_];
__device__ float g_hps[N_ * H_];
__device__ float g_hns[N_ * H_];
__device__ float g_h  [N_ * H_];
__device__ float g_gps[N_ * O_];
__device__ float g_gns[N_ * O_];
struct EdgeRec { int s; int t; float scale; int pad; };
__device__ EdgeRec g_edge[E_];          // 25.6 MB packed edge metadata

// ---------------- helpers ------------------------------------------------------
__device__ __forceinline__ void red_add_v4(float* p, float a, float b, float c, float d) {
    asm volatile("red.global.add.v4.f32 [%0], {%1,%2,%3,%4};"
                 :: "l"(p), "f"(a), "f"(b), "f"(c), "f"(d) : "memory");
}

__device__ __forceinline__ void fma2(unsigned long long& acc,
                                     unsigned long long w,
                                     unsigned long long xx) {
    asm("fma.rn.f32x2 %0, %1, %2, %0;" : "+l"(acc) : "l"(w), "l"(xx));
}

__device__ __forceinline__ unsigned long long packf2(float a, float b) {
    unsigned long long r;
    asm("mov.b64 %0, {%1, %2};" : "=l"(r) : "f"(a), "f"(b));
    return r;
}

__device__ __forceinline__ void unpack2(unsigned long long v, float& lo, float& hi) {
    asm("mov.b64 {%0, %1}, %2;" : "=f"(lo), "=f"(hi) : "l"(v));
}

// ---------------- degree / dinv / edge prep -------------------------------------
__global__ void k_zero_deg(int n) {
    int i = blockIdx.x * blockDim.x + threadIdx.x;
    if (i < n) { g_degp[i] = 0.f; g_degn[i] = 0.f; }
}

__global__ void k_deg(const int* __restrict__ ei, const float* __restrict__ w, int E) {
    int e = blockIdx.x * blockDim.x + threadIdx.x;
    if (e >= E) return;
    float we = w[e];
    int t = ei[E + e];
    if (we > 0.f)      atomicAdd(&g_degp[t], we);
    else if (we < 0.f) atomicAdd(&g_degn[t], -we);
}

__global__ void k_dinv(int n) {
    int i = blockIdx.x * blockDim.x + threadIdx.x;
    if (i < n) {
        g_dinvp[i] = rsqrtf(g_degp[i] + 1.0f);
        g_dinvn[i] = rsqrtf(g_degn[i] + 1.0f);
    }
}

// build packed per-edge record: scale = we * dinv_sel[t]; sign(scale) selects subgraph
__global__ void k_prep(const int* __restrict__ ei, const float* __restrict__ w, int E) {
    int e = blockIdx.x * blockDim.x + threadIdx.x;
    if (e >= E) return;
    int s = ei[e];
    int t = ei[E + e];
    float we = w[e];
    float d = (we >= 0.f) ? g_dinvp[t] : g_dinvn[t];
    EdgeRec r; r.s = s; r.t = t; r.scale = we * d; r.pad = 0;
    g_edge[e] = r;
}

// ================ GEMM layer 1: x[N,64] -> (hps,hns,h)[N,128] ====================
#define SMEM1 (32 * 64 * 16 + 64 * 64 * 4 + 2 * 64 * 4)   // 49664 B
__global__ __launch_bounds__(128) void k_gemm1(
    const float* __restrict__ x,
    const float* __restrict__ W1p, const float* __restrict__ b1p,
    const float* __restrict__ W1n, const float* __restrict__ b1n, int n)
{
    extern __shared__ char sm[];
    ulonglong2* ws = (ulonglong2*)sm;                       // [32 k2][64 c]
    float* xs  = (float*)(sm + 32 * 64 * 16);               // [64 r][64 k]
    float* sdp = (float*)(sm + 32 * 64 * 16 + 64 * 64 * 4); // [64]
    float* sdn = sdp + 64;

    const int tid = threadIdx.x;
    const int tx = tid & 63;
    const int ty = tid >> 6;
    const int rb  = blockIdx.x >> 1;
    const int colbase = (blockIdx.x & 1) * 64;
    const int base = rb * 64;

    for (int i = tid; i < 16 * 64; i += 128) {
        int k4 = i & 15;
        int c  = i >> 4;
        int col = colbase + c;
        float4 wp = *(const float4*)&W1p[col * IN_ + 4 * k4];
        float4 wn = *(const float4*)&W1n[col * IN_ + 4 * k4];
        int k2a = 2 * k4, k2b = 2 * k4 + 1;
        ws[k2a * 64 + (c ^ (k2a & 15))] =
            make_ulonglong2(packf2(wp.x, wp.y), packf2(wn.x, wn.y));
        ws[k2b * 64 + (c ^ (k2b & 15))] =
            make_ulonglong2(packf2(wp.z, wp.w), packf2(wn.z, wn.w));
    }
    for (int i = tid; i < 64 * 16; i += 128) {
        int r = i >> 4;
        int row = base + r;
        float4 v = make_float4(0.f, 0.f, 0.f, 0.f);
        if (row < n) v = ((const float4*)x)[row * 16 + (i & 15)];
        ((float4*)xs)[i] = v;
    }
    if (tid < 64) {
        int row = base + tid;
        sdp[tid] = (row < n) ? g_dinvp[row] : 0.f;
        sdn[tid] = (row < n) ? g_dinvn[row] : 0.f;
    }
    __syncthreads();

    const int col = colbase + tx;
    const float bp = b1p[col], bn = b1n[col];

    for (int chunk = 0; chunk < 4; chunk++) {
        const int rbase = ty * 32 + chunk * 8;
        const float* xrow = xs + rbase * 64;
        unsigned long long accp[8], accn[8];
        #pragma unroll
        for (int r = 0; r < 8; r++) { accp[r] = 0ull; accn[r] = 0ull; }

        #pragma unroll 4
        for (int k4 = 0; k4 < 16; k4++) {
            const int k2a = 2 * k4, k2b = 2 * k4 + 1;
            ulonglong2 w0 = ws[k2a * 64 + (tx ^ (k2a & 15))];
            ulonglong2 w1 = ws[k2b * 64 + (tx ^ (k2b & 15))];
            #pragma unroll
            for (int r = 0; r < 8; r++) {
                float4 xv = *(const float4*)&xrow[r * 64 + 4 * k4];
                unsigned long long x0 = packf2(xv.x, xv.y);
                unsigned long long x1 = packf2(xv.z, xv.w);
                fma2(accp[r], w0.x, x0);
                fma2(accn[r], w0.y, x0);
                fma2(accp[r], w1.x, x1);
                fma2(accn[r], w1.y, x1);
            }
        }

        #pragma unroll
        for (int r = 0; r < 8; r++) {
            int rr = rbase + r;
            int row = base + rr;
            if (row >= n) continue;
            float pl, ph, ql, qh;
            unpack2(accp[r], pl, ph);
            unpack2(accn[r], ql, qh);
            float ap = pl + ph, an = ql + qh;
            float dp = sdp[rr], dn = sdn[rr];
            g_hps[row * H_ + col] = ap * dp;
            g_hns[row * H_ + col] = an * dn;
            g_h  [row * H_ + col] = ap * dp * dp + bp - an * dn * dn - bn;
        }
    }
}

// ---------------- edge aggregation layer 1 (warp per edge, F=128) ---------------
__global__ __launch_bounds__(256) void k_edge1(int E)
{
    int wid = (blockIdx.x * blockDim.x + threadIdx.x) >> 5;
    if (wid >= E) return;
    int lane = threadIdx.x & 31;
    int4 er = __ldg((const int4*)&g_edge[wid]);     // {s, t, scale, pad}
    int s = er.x, t = er.y;
    float scale = __int_as_float(er.z);
    const float* src = (scale >= 0.f) ? g_hps : g_hns;
    float4 v = __ldg((const float4*)(src + s * H_) + lane);
    red_add_v4(g_h + t * H_ + lane * 4,
               v.x * scale, v.y * scale, v.z * scale, v.w * scale);
}

// ================ GEMM layer 2: relu(h)[N,128] -> (gps,gns,out)[N,64] ============
#define SMEM2 (64 * 64 * 16 + 64 * 128 * 4 + 2 * 64 * 4)   // 98816 B
__global__ __launch_bounds__(128) void k_gemm2(
    const float* __restrict__ W2p, const float* __restrict__ b2p,
    const float* __restrict__ W2n, const float* __restrict__ b2n,
    float* __restrict__ out, int n)
{
    extern __shared__ char sm[];
    ulonglong2* ws = (ulonglong2*)sm;                        // [64 k2][64 c]
    float* xs  = (float*)(sm + 64 * 64 * 16);                // [64 r][128 k]
    float* sdp = (float*)(sm + 64 * 64 * 16 + 64 * 128 * 4); // [64]
    float* sdn = sdp + 64;

    const int tid = threadIdx.x;
    const int tx = tid & 63;
    const int ty = tid >> 6;
    const int base = blockIdx.x * 64;

    for (int i = tid; i < 32 * 64; i += 128) {
        int k4 = i & 31;
        int c  = i >> 5;
        float4 wp = *(const float4*)&W2p[c * H_ + 4 * k4];
        float4 wn = *(const float4*)&W2n[c * H_ + 4 * k4];
        int k2a = 2 * k4, k2b = 2 * k4 + 1;
        ws[k2a * 64 + (c ^ (k2a & 15))] =
            make_ulonglong2(packf2(wp.x, wp.y), packf2(wn.x, wn.y));
        ws[k2b * 64 + (c ^ (k2b & 15))] =
            make_ulonglong2(packf2(wp.z, wp.w), packf2(wn.z, wn.w));
    }
    for (int i = tid; i < 64 * 32; i += 128) {
        int r = i >> 5;
        int row = base + r;
        float4 v = make_float4(0.f, 0.f, 0.f, 0.f);
        if (row < n) {
            v = ((const float4*)g_h)[row * 32 + (i & 31)];
            v.x = fmaxf(v.x, 0.f); v.y = fmaxf(v.y, 0.f);
            v.z = fmaxf(v.z, 0.f); v.w = fmaxf(v.w, 0.f);
        }
        ((float4*)xs)[i] = v;
    }
    if (tid < 64) {
        int row = base + tid;
        sdp[tid] = (row < n) ? g_dinvp[row] : 0.f;
        sdn[tid] = (row < n) ? g_dinvn[row] : 0.f;
    }
    __syncthreads();

    const float bp = b2p[tx], bn = b2n[tx];

    for (int chunk = 0; chunk < 4; chunk++) {
        const int rbase = ty * 32 + chunk * 8;
        const float* xrow = xs + rbase * 128;
        unsigned long long accp[8], accn[8];
        #pragma unroll
        for (int r = 0; r < 8; r++) { accp[r] = 0ull; accn[r] = 0ull; }

        #pragma unroll 8
        for (int k4 = 0; k4 < 32; k4++) {
            const int k2a = 2 * k4, k2b = 2 * k4 + 1;
            ulonglong2 w0 = ws[k2a * 64 + (tx ^ (k2a & 15))];
            ulonglong2 w1 = ws[k2b * 64 + (tx ^ (k2b & 15))];
            #pragma unroll
            for (int r = 0; r < 8; r++) {
                float4 xv = *(const float4*)&xrow[r * 128 + 4 * k4];
                unsigned long long x0 = packf2(xv.x, xv.y);
                unsigned long long x1 = packf2(xv.z, xv.w);
                fma2(accp[r], w0.x, x0);
                fma2(accn[r], w0.y, x0);
                fma2(accp[r], w1.x, x1);
                fma2(accn[r], w1.y, x1);
            }
        }

        #pragma unroll
        for (int r = 0; r < 8; r++) {
            int rr = rbase + r;
            int row = base + rr;
            if (row >= n) continue;
            float pl, ph, ql, qh;
            unpack2(accp[r], pl, ph);
            unpack2(accn[r], ql, qh);
            float ap = pl + ph, an = ql + qh;
            float dp = sdp[rr], dn = sdn[rr];
            g_gps[row * O_ + tx] = ap * dp;
            g_gns[row * O_ + tx] = an * dn;
            out  [row * O_ + tx] = ap * dp * dp + bp - an * dn * dn - bn;
        }
    }
}

// ---------------- edge aggregation layer 2 (16 lanes per edge, F=64) ------------
__global__ __launch_bounds__(256) void k_edge2(float* __restrict__ out, int E)
{
    int gid = blockIdx.x * blockDim.x + threadIdx.x;
    int e = gid >> 4;
    if (e >= E) return;
    int sub = gid & 15;
    int4 er = __ldg((const int4*)&g_edge[e]);
    int s = er.x, t = er.y;
    float scale = __int_as_float(er.z);
    const float* src = (scale >= 0.f) ? g_gps : g_gns;
    float4 v = __ldg((const float4*)(src + s * O_) + sub);
    red_add_v4(out + t * O_ + sub * 4,
               v.x * scale, v.y * scale, v.z * scale, v.w * scale);
}

__global__ void k_relu_out(float* __restrict__ out, int n4) {
    int i = blockIdx.x * blockDim.x + threadIdx.x;
    if (i >= n4) return;
    float4 v = ((float4*)out)[i];
    v.x = fmaxf(v.x, 0.f); v.y = fmaxf(v.y, 0.f);
    v.z = fmaxf(v.z, 0.f); v.w = fmaxf(v.w, 0.f);
    ((float4*)out)[i] = v;
}

// ---------------- launch ---------------------------------------------------------
extern "C" void kernel_launch(void* const* d_in, const int* in_sizes, int n_in,
                              void* d_out, int out_size)
{
    const float* x   = (const float*)d_in[0];
    const int*   ei  = (const int*)  d_in[1];
    const float* w   = (const float*)d_in[2];
    const float* W1p = (const float*)d_in[3];
    const float* b1p = (const float*)d_in[4];
    const float* W1n = (const float*)d_in[5];
    const float* b1n = (const float*)d_in[6];
    const float* W2p = (const float*)d_in[7];
    const float* b2p = (const float*)d_in[8];
    const float* W2n = (const float*)d_in[9];
    const float* b2n = (const float*)d_in[10];
    float* out = (float*)d_out;

    const int n = in_sizes[0] / IN_;
    const int E = in_sizes[2];
    const int rowBlocks = (n + 63) / 64;

    cudaFuncSetAttribute(k_gemm1, cudaFuncAttributeMaxDynamicSharedMemorySize, SMEM1);
    cudaFuncSetAttribute(k_gemm2, cudaFuncAttributeMaxDynamicSharedMemorySize, SMEM2);

    k_zero_deg<<<(n + 255) / 256, 256>>>(n);
    k_deg<<<(E + 255) / 256, 256>>>(ei, w, E);
    k_dinv<<<(n + 255) / 256, 256>>>(n);
    k_prep<<<(E + 255) / 256, 256>>>(ei, w, E);

    k_gemm1<<<rowBlocks * 2, 128, SMEM1>>>(x, W1p, b1p, W1n, b1n, n);
    k_edge1<<<(E + 7) / 8, 256>>>(E);

    k_gemm2<<<rowBlocks, 128, SMEM2>>>(W2p, b2p, W2n, b2n, out, n);
    k_edge2<<<(E * 16 + 255) / 256, 256>>>(out, E);
    k_relu_out<<<(n * O_ / 4 + 255) / 256, 256>>>(out, n * O_ / 4);
}

// round 7
// speedup vs baseline: 2.1935x; 1.1993x over previous
#include <cuda_runtime.h>
#include <cuda_bf16.h>

#define N_   100000
#define E_   1600000
#define IN_  64
#define H_   128
#define O_   64

// ---------------- scratch -------------------------------------------------------
__device__ float g_degp[N_];
__device__ float g_degn[N_];
__device__ float g_dinvp[N_];
__device__ float g_dinvn[N_];
__device__ int   g_cnt [N_];        // in-degree (int) histogram
__device__ int   g_cur [N_];        // scatter cursors
__device__ int   g_off [N_ + 1];    // CSR offsets
__device__ int2  g_eidx[E_];        // CSR records: {src, scale}
__device__ float g_hps[N_ * H_];
__device__ float g_hns[N_ * H_];
__device__ float g_h  [N_ * H_];
__device__ float g_gps[N_ * O_];
__device__ float g_gns[N_ * O_];

// ---------------- helpers ------------------------------------------------------
__device__ __forceinline__ void fma2(unsigned long long& acc,
                                     unsigned long long w,
                                     unsigned long long xx) {
    asm("fma.rn.f32x2 %0, %1, %2, %0;" : "+l"(acc) : "l"(w), "l"(xx));
}

__device__ __forceinline__ unsigned long long packf2(float a, float b) {
    unsigned long long r;
    asm("mov.b64 %0, {%1, %2};" : "=l"(r) : "f"(a), "f"(b));
    return r;
}

__device__ __forceinline__ void unpack2(unsigned long long v, float& lo, float& hi) {
    asm("mov.b64 {%0, %1}, %2;" : "=f"(lo), "=f"(hi) : "l"(v));
}

// ---------------- degree / dinv / CSR build -------------------------------------
__global__ void k_zero(int n) {
    int i = blockIdx.x * blockDim.x + threadIdx.x;
    if (i < n) { g_degp[i] = 0.f; g_degn[i] = 0.f; g_cnt[i] = 0; g_cur[i] = 0; }
}

__global__ void k_deg(const int* __restrict__ ei, const float* __restrict__ w, int E) {
    int e = blockIdx.x * blockDim.x + threadIdx.x;
    if (e >= E) return;
    float we = w[e];
    int t = ei[E + e];
    if (we > 0.f)      atomicAdd(&g_degp[t], we);
    else if (we < 0.f) atomicAdd(&g_degn[t], -we);
    atomicAdd(&g_cnt[t], 1);
}

__global__ void k_dinv(int n) {
    int i = blockIdx.x * blockDim.x + threadIdx.x;
    if (i < n) {
        g_dinvp[i] = rsqrtf(g_degp[i] + 1.0f);
        g_dinvn[i] = rsqrtf(g_degn[i] + 1.0f);
    }
}

// single-block exclusive scan of g_cnt -> g_off
__global__ __launch_bounds__(1024) void k_scan(int n) {
    __shared__ int carry;
    __shared__ int warpsum[32];
    const int tid = threadIdx.x;
    const int lane = tid & 31;
    const int wid = tid >> 5;
    if (tid == 0) carry = 0;
    __syncthreads();
    for (int base = 0; base < n; base += 1024) {
        int i = base + tid;
        int v = (i < n) ? g_cnt[i] : 0;
        int x = v;
        #pragma unroll
        for (int o = 1; o < 32; o <<= 1) {
            int y = __shfl_up_sync(~0u, x, o);
            if (lane >= o) x += y;
        }
        if (lane == 31) warpsum[wid] = x;
        __syncthreads();
        if (wid == 0) {
            int s = warpsum[lane];
            #pragma unroll
            for (int o = 1; o < 32; o <<= 1) {
                int y = __shfl_up_sync(~0u, s, o);
                if (lane >= o) s += y;
            }
            warpsum[lane] = s;
        }
        __syncthreads();
        int pref = (wid > 0 ? warpsum[wid - 1] : 0) + carry;
        if (i < n) g_off[i] = pref + x - v;   // exclusive
        __syncthreads();
        if (tid == 1023) carry = pref + x;
        __syncthreads();
    }
    if (threadIdx.x == 0) g_off[n] = carry;
}

__global__ void k_scatter(const int* __restrict__ ei, const float* __restrict__ w, int E) {
    int e = blockIdx.x * blockDim.x + threadIdx.x;
    if (e >= E) return;
    int s = ei[e];
    int t = ei[E + e];
    float we = w[e];
    float d = (we >= 0.f) ? g_dinvp[t] : g_dinvn[t];
    int pos = g_off[t] + atomicAdd(&g_cur[t], 1);
    g_eidx[pos] = make_int2(s, __float_as_int(we * d));
}

// ================ GEMM layer 1: x[N,64] -> (hps,hns,h)[N,128] ====================
#define SMEM1 (32 * 64 * 16 + 64 * 64 * 4 + 2 * 64 * 4)   // 49664 B
__global__ __launch_bounds__(128) void k_gemm1(
    const float* __restrict__ x,
    const float* __restrict__ W1p, const float* __restrict__ b1p,
    const float* __restrict__ W1n, const float* __restrict__ b1n, int n)
{
    extern __shared__ char sm[];
    ulonglong2* ws = (ulonglong2*)sm;                       // [32 k2][64 c]
    float* xs  = (float*)(sm + 32 * 64 * 16);               // [64 r][64 k]
    float* sdp = (float*)(sm + 32 * 64 * 16 + 64 * 64 * 4); // [64]
    float* sdn = sdp + 64;

    const int tid = threadIdx.x;
    const int tx = tid & 63;
    const int ty = tid >> 6;
    const int rb  = blockIdx.x >> 1;
    const int colbase = (blockIdx.x & 1) * 64;
    const int base = rb * 64;

    for (int i = tid; i < 16 * 64; i += 128) {
        int k4 = i & 15;
        int c  = i >> 4;
        int col = colbase + c;
        float4 wp = *(const float4*)&W1p[col * IN_ + 4 * k4];
        float4 wn = *(const float4*)&W1n[col * IN_ + 4 * k4];
        int k2a = 2 * k4, k2b = 2 * k4 + 1;
        ws[k2a * 64 + (c ^ (k2a & 15))] =
            make_ulonglong2(packf2(wp.x, wp.y), packf2(wn.x, wn.y));
        ws[k2b * 64 + (c ^ (k2b & 15))] =
            make_ulonglong2(packf2(wp.z, wp.w), packf2(wn.z, wn.w));
    }
    for (int i = tid; i < 64 * 16; i += 128) {
        int r = i >> 4;
        int row = base + r;
        float4 v = make_float4(0.f, 0.f, 0.f, 0.f);
        if (row < n) v = ((const float4*)x)[row * 16 + (i & 15)];
        ((float4*)xs)[i] = v;
    }
    if (tid < 64) {
        int row = base + tid;
        sdp[tid] = (row < n) ? g_dinvp[row] : 0.f;
        sdn[tid] = (row < n) ? g_dinvn[row] : 0.f;
    }
    __syncthreads();

    const int col = colbase + tx;
    const float bp = b1p[col], bn = b1n[col];

    for (int chunk = 0; chunk < 4; chunk++) {
        const int rbase = ty * 32 + chunk * 8;
        const float* xrow = xs + rbase * 64;
        unsigned long long accp[8], accn[8];
        #pragma unroll
        for (int r = 0; r < 8; r++) { accp[r] = 0ull; accn[r] = 0ull; }

        #pragma unroll 4
        for (int k4 = 0; k4 < 16; k4++) {
            const int k2a = 2 * k4, k2b = 2 * k4 + 1;
            ulonglong2 w0 = ws[k2a * 64 + (tx ^ (k2a & 15))];
            ulonglong2 w1 = ws[k2b * 64 + (tx ^ (k2b & 15))];
            #pragma unroll
            for (int r = 0; r < 8; r++) {
                float4 xv = *(const float4*)&xrow[r * 64 + 4 * k4];
                unsigned long long x0 = packf2(xv.x, xv.y);
                unsigned long long x1 = packf2(xv.z, xv.w);
                fma2(accp[r], w0.x, x0);
                fma2(accn[r], w0.y, x0);
                fma2(accp[r], w1.x, x1);
                fma2(accn[r], w1.y, x1);
            }
        }

        #pragma unroll
        for (int r = 0; r < 8; r++) {
            int rr = rbase + r;
            int row = base + rr;
            if (row >= n) continue;
            float pl, ph, ql, qh;
            unpack2(accp[r], pl, ph);
            unpack2(accn[r], ql, qh);
            float ap = pl + ph, an = ql + qh;
            float dp = sdp[rr], dn = sdn[rr];
            g_hps[row * H_ + col] = ap * dp;
            g_hns[row * H_ + col] = an * dn;
            g_h  [row * H_ + col] = ap * dp * dp + bp - an * dn * dn - bn;
        }
    }
}

// ---------------- edge aggregation layer 1: warp per node (F=128) ---------------
__global__ __launch_bounds__(256) void k_edge1(int n)
{
    int v = (blockIdx.x * blockDim.x + threadIdx.x) >> 5;
    if (v >= n) return;
    int lane = threadIdx.x & 31;
    int beg = g_off[v], end = g_off[v + 1];
    float4 acc = *(float4*)&g_h[v * H_ + lane * 4];   // self-loop + bias init
    for (int i = beg; i < end; i++) {
        int2 er = __ldg(&g_eidx[i]);
        float scale = __int_as_float(er.y);
        const float* src = (scale >= 0.f) ? g_hps : g_hns;
        float4 xv = __ldg((const float4*)(src + er.x * H_) + lane);
        acc.x += xv.x * scale; acc.y += xv.y * scale;
        acc.z += xv.z * scale; acc.w += xv.w * scale;
    }
    *(float4*)&g_h[v * H_ + lane * 4] = acc;
}

// ================ GEMM layer 2: relu(h)[N,128] -> (gps,gns,out)[N,64] ============
#define SMEM2 (64 * 64 * 16 + 64 * 128 * 4 + 2 * 64 * 4)   // 98816 B
__global__ __launch_bounds__(128) void k_gemm2(
    const float* __restrict__ W2p, const float* __restrict__ b2p,
    const float* __restrict__ W2n, const float* __restrict__ b2n,
    float* __restrict__ out, int n)
{
    extern __shared__ char sm[];
    ulonglong2* ws = (ulonglong2*)sm;                        // [64 k2][64 c]
    float* xs  = (float*)(sm + 64 * 64 * 16);                // [64 r][128 k]
    float* sdp = (float*)(sm + 64 * 64 * 16 + 64 * 128 * 4); // [64]
    float* sdn = sdp + 64;

    const int tid = threadIdx.x;
    const int tx = tid & 63;
    const int ty = tid >> 6;
    const int base = blockIdx.x * 64;

    for (int i = tid; i < 32 * 64; i += 128) {
        int k4 = i & 31;
        int c  = i >> 5;
        float4 wp = *(const float4*)&W2p[c * H_ + 4 * k4];
        float4 wn = *(const float4*)&W2n[c * H_ + 4 * k4];
        int k2a = 2 * k4, k2b = 2 * k4 + 1;
        ws[k2a * 64 + (c ^ (k2a & 15))] =
            make_ulonglong2(packf2(wp.x, wp.y), packf2(wn.x, wn.y));
        ws[k2b * 64 + (c ^ (k2b & 15))] =
            make_ulonglong2(packf2(wp.z, wp.w), packf2(wn.z, wn.w));
    }
    for (int i = tid; i < 64 * 32; i += 128) {
        int r = i >> 5;
        int row = base + r;
        float4 v = make_float4(0.f, 0.f, 0.f, 0.f);
        if (row < n) {
            v = ((const float4*)g_h)[row * 32 + (i & 31)];
            v.x = fmaxf(v.x, 0.f); v.y = fmaxf(v.y, 0.f);
            v.z = fmaxf(v.z, 0.f); v.w = fmaxf(v.w, 0.f);
        }
        ((float4*)xs)[i] = v;
    }
    if (tid < 64) {
        int row = base + tid;
        sdp[tid] = (row < n) ? g_dinvp[row] : 0.f;
        sdn[tid] = (row < n) ? g_dinvn[row] : 0.f;
    }
    __syncthreads();

    const float bp = b2p[tx], bn = b2n[tx];

    for (int chunk = 0; chunk < 4; chunk++) {
        const int rbase = ty * 32 + chunk * 8;
        const float* xrow = xs + rbase * 128;
        unsigned long long accp[8], accn[8];
        #pragma unroll
        for (int r = 0; r < 8; r++) { accp[r] = 0ull; accn[r] = 0ull; }

        #pragma unroll 8
        for (int k4 = 0; k4 < 32; k4++) {
            const int k2a = 2 * k4, k2b = 2 * k4 + 1;
            ulonglong2 w0 = ws[k2a * 64 + (tx ^ (k2a & 15))];
            ulonglong2 w1 = ws[k2b * 64 + (tx ^ (k2b & 15))];
            #pragma unroll
            for (int r = 0; r < 8; r++) {
                float4 xv = *(const float4*)&xrow[r * 128 + 4 * k4];
                unsigned long long x0 = packf2(xv.x, xv.y);
                unsigned long long x1 = packf2(xv.z, xv.w);
                fma2(accp[r], w0.x, x0);
                fma2(accn[r], w0.y, x0);
                fma2(accp[r], w1.x, x1);
                fma2(accn[r], w1.y, x1);
            }
        }

        #pragma unroll
        for (int r = 0; r < 8; r++) {
            int rr = rbase + r;
            int row = base + rr;
            if (row >= n) continue;
            float pl, ph, ql, qh;
            unpack2(accp[r], pl, ph);
            unpack2(accn[r], ql, qh);
            float ap = pl + ph, an = ql + qh;
            float dp = sdp[rr], dn = sdn[rr];
            g_gps[row * O_ + tx] = ap * dp;
            g_gns[row * O_ + tx] = an * dn;
            out  [row * O_ + tx] = ap * dp * dp + bp - an * dn * dn - bn;
        }
    }
}

// ---------------- edge aggregation layer 2: warp per node (F=64), fused ReLU ----
__global__ __launch_bounds__(256) void k_edge2(float* __restrict__ out, int n)
{
    int v = (blockIdx.x * blockDim.x + threadIdx.x) >> 5;
    if (v >= n) return;
    int lane = threadIdx.x & 31;
    int half = lane >> 4;      // 0: even edges, 1: odd edges
    int f = lane & 15;         // feature group (4 floats each)
    int beg = g_off[v], end = g_off[v + 1];
    float4 acc = make_float4(0.f, 0.f, 0.f, 0.f);
    for (int i = beg + half; i < end; i += 2) {
        int2 er = __ldg(&g_eidx[i]);
        float scale = __int_as_float(er.y);
        const float* src = (scale >= 0.f) ? g_gps : g_gns;
        float4 xv = __ldg((const float4*)(src + er.x * O_) + f);
        acc.x += xv.x * scale; acc.y += xv.y * scale;
        acc.z += xv.z * scale; acc.w += xv.w * scale;
    }
    __syncwarp();
    acc.x += __shfl_xor_sync(~0u, acc.x, 16);
    acc.y += __shfl_xor_sync(~0u, acc.y, 16);
    acc.z += __shfl_xor_sync(~0u, acc.z, 16);
    acc.w += __shfl_xor_sync(~0u, acc.w, 16);
    if (half == 0) {
        float4 self = *(float4*)&out[v * O_ + f * 4];   // self + bias from gemm2
        acc.x = fmaxf(acc.x + self.x, 0.f);
        acc.y = fmaxf(acc.y + self.y, 0.f);
        acc.z = fmaxf(acc.z + self.z, 0.f);
        acc.w = fmaxf(acc.w + self.w, 0.f);
        *(float4*)&out[v * O_ + f * 4] = acc;
    }
}

// ---------------- launch ---------------------------------------------------------
extern "C" void kernel_launch(void* const* d_in, const int* in_sizes, int n_in,
                              void* d_out, int out_size)
{
    const float* x   = (const float*)d_in[0];
    const int*   ei  = (const int*)  d_in[1];
    const float* w   = (const float*)d_in[2];
    const float* W1p = (const float*)d_in[3];
    const float* b1p = (const float*)d_in[4];
    const float* W1n = (const float*)d_in[5];
    const float* b1n = (const float*)d_in[6];
    const float* W2p = (const float*)d_in[7];
    const float* b2p = (const float*)d_in[8];
    const float* W2n = (const float*)d_in[9];
    const float* b2n = (const float*)d_in[10];
    float* out = (float*)d_out;

    const int n = in_sizes[0] / IN_;
    const int E = in_sizes[2];
    const int rowBlocks = (n + 63) / 64;

    cudaFuncSetAttribute(k_gemm1, cudaFuncAttributeMaxDynamicSharedMemorySize, SMEM1);
    cudaFuncSetAttribute(k_gemm2, cudaFuncAttributeMaxDynamicSharedMemorySize, SMEM2);

    k_zero<<<(n + 255) / 256, 256>>>(n);
    k_deg<<<(E + 255) / 256, 256>>>(ei, w, E);
    k_dinv<<<(n + 255) / 256, 256>>>(n);
    k_scan<<<1, 1024>>>(n);
    k_scatter<<<(E + 255) / 256, 256>>>(ei, w, E);

    k_gemm1<<<rowBlocks * 2, 128, SMEM1>>>(x, W1p, b1p, W1n, b1n, n);
    k_edge1<<<(n * 32 + 255) / 256, 256>>>(n);

    k_gemm2<<<rowBlocks, 128, SMEM2>>>(W2p, b2p, W2n, b2n, out, n);
    k_edge2<<<(n * 32 + 255) / 256, 256>>>(out, n);
}

// round 8
// speedup vs baseline: 2.5219x; 1.1497x over previous
#include <cuda_runtime.h>
#include <cuda_bf16.h>

#define N_   100000
#define E_   1600000
#define IN_  64
#define H_   128
#define O_   64
#define SCAN_BLK 1024   // elements per scan block

// ---------------- scratch -------------------------------------------------------
__device__ float g_degp[N_];
__device__ float g_degn[N_];
__device__ float g_dinvp[N_];
__device__ float g_dinvn[N_];
__device__ int   g_cnt [N_];        // in-degree histogram
__device__ int   g_cur [N_];        // scatter cursors
__device__ int   g_off [N_ + 1];    // CSR offsets
__device__ int   g_bsum[(N_ + SCAN_BLK - 1) / SCAN_BLK];   // per-block sums
__device__ int   g_bpre[(N_ + SCAN_BLK - 1) / SCAN_BLK];   // block prefix
__device__ int2  g_eidx[E_];        // CSR records: {src, scale}
__device__ float g_hps[N_ * H_];
__device__ float g_hns[N_ * H_];
__device__ float g_h  [N_ * H_];
__device__ float g_gps[N_ * O_];
__device__ float g_gns[N_ * O_];

// ---------------- helpers ------------------------------------------------------
__device__ __forceinline__ void fma2(unsigned long long& acc,
                                     unsigned long long w,
                                     unsigned long long xx) {
    asm("fma.rn.f32x2 %0, %1, %2, %0;" : "+l"(acc) : "l"(w), "l"(xx));
}

__device__ __forceinline__ unsigned long long packf2(float a, float b) {
    unsigned long long r;
    asm("mov.b64 %0, {%1, %2};" : "=l"(r) : "f"(a), "f"(b));
    return r;
}

__device__ __forceinline__ void unpack2(unsigned long long v, float& lo, float& hi) {
    asm("mov.b64 {%0, %1}, %2;" : "=f"(lo), "=f"(hi) : "l"(v));
}

// ---------------- degree / dinv / CSR build -------------------------------------
__global__ void k_zero(int n) {
    int i = blockIdx.x * blockDim.x + threadIdx.x;
    if (i < n) { g_degp[i] = 0.f; g_degn[i] = 0.f; g_cnt[i] = 0; g_cur[i] = 0; }
}

__global__ void k_deg(const int* __restrict__ ei, const float* __restrict__ w, int E) {
    int e = blockIdx.x * blockDim.x + threadIdx.x;
    if (e >= E) return;
    float we = w[e];
    int t = ei[E + e];
    if (we > 0.f)      atomicAdd(&g_degp[t], we);
    else if (we < 0.f) atomicAdd(&g_degn[t], -we);
    atomicAdd(&g_cnt[t], 1);
}

__global__ void k_dinv(int n) {
    int i = blockIdx.x * blockDim.x + threadIdx.x;
    if (i < n) {
        g_dinvp[i] = rsqrtf(g_degp[i] + 1.0f);
        g_dinvn[i] = rsqrtf(g_degn[i] + 1.0f);
    }
}

// phase 1: per-block sums over SCAN_BLK elements (256 threads x 4)
__global__ __launch_bounds__(256) void k_bsum(int n) {
    __shared__ int wsum[8];
    const int b = blockIdx.x;
    const int tid = threadIdx.x;
    int s = 0;
    #pragma unroll
    for (int j = 0; j < 4; j++) {
        int i = b * SCAN_BLK + j * 256 + tid;
        if (i < n) s += g_cnt[i];
    }
    #pragma unroll
    for (int o = 16; o > 0; o >>= 1) s += __shfl_xor_sync(~0u, s, o);
    if ((tid & 31) == 0) wsum[tid >> 5] = s;
    __syncthreads();
    if (tid == 0) {
        int t = 0;
        #pragma unroll
        for (int k = 0; k < 8; k++) t += wsum[k];
        g_bsum[b] = t;
    }
}

// phase 2: single small block scans block sums (B <= 1024)
__global__ __launch_bounds__(128) void k_bscan(int B, int n) {
    __shared__ int sh[1024];
    for (int i = threadIdx.x; i < B; i += 128) sh[i] = g_bsum[i];
    __syncthreads();
    if (threadIdx.x == 0) {
        int run = 0;
        for (int i = 0; i < B; i++) { int v = sh[i]; sh[i] = run; run += v; }
        g_off[n] = run;
    }
    __syncthreads();
    for (int i = threadIdx.x; i < B; i += 128) g_bpre[i] = sh[i];
}

// phase 3: per-block local exclusive scan + block prefix
__global__ __launch_bounds__(256) void k_offsets(int n) {
    __shared__ int wsum[8];
    const int b = blockIdx.x;
    const int tid = threadIdx.x;
    const int lane = tid & 31;
    const int wid = tid >> 5;
    const int i0 = b * SCAN_BLK + tid * 4;

    int c0 = 0, c1 = 0, c2 = 0, c3 = 0;
    if (i0 + 3 < n) {
        int4 c = *(const int4*)&g_cnt[i0];
        c0 = c.x; c1 = c.y; c2 = c.z; c3 = c.w;
    } else {
        if (i0     < n) c0 = g_cnt[i0];
        if (i0 + 1 < n) c1 = g_cnt[i0 + 1];
        if (i0 + 2 < n) c2 = g_cnt[i0 + 2];
        if (i0 + 3 < n) c3 = g_cnt[i0 + 3];
    }
    int tsum = c0 + c1 + c2 + c3;

    int x = tsum;
    #pragma unroll
    for (int o = 1; o < 32; o <<= 1) {
        int y = __shfl_up_sync(~0u, x, o);
        if (lane >= o) x += y;
    }
    if (lane == 31) wsum[wid] = x;
    __syncthreads();
    if (tid == 0) {
        int run = 0;
        #pragma unroll
        for (int k = 0; k < 8; k++) { int v = wsum[k]; wsum[k] = run; run += v; }
    }
    __syncthreads();

    int pre = g_bpre[b] + wsum[wid] + (x - tsum);   // exclusive before element i0
    if (i0 + 3 < n) {
        int4 o4 = make_int4(pre, pre + c0, pre + c0 + c1, pre + c0 + c1 + c2);
        *(int4*)&g_off[i0] = o4;
    } else {
        if (i0     < n) g_off[i0]     = pre;
        if (i0 + 1 < n) g_off[i0 + 1] = pre + c0;
        if (i0 + 2 < n) g_off[i0 + 2] = pre + c0 + c1;
        if (i0 + 3 < n) g_off[i0 + 3] = pre + c0 + c1 + c2;
    }
}

__global__ void k_scatter(const int* __restrict__ ei, const float* __restrict__ w, int E) {
    int e = blockIdx.x * blockDim.x + threadIdx.x;
    if (e >= E) return;
    int s = ei[e];
    int t = ei[E + e];
    float we = w[e];
    float d = (we >= 0.f) ? g_dinvp[t] : g_dinvn[t];
    int pos = g_off[t] + atomicAdd(&g_cur[t], 1);
    g_eidx[pos] = make_int2(s, __float_as_int(we * d));
}

// ================ GEMM layer 1: x[N,64] -> (hps,hns,h)[N,128] ====================
#define SMEM1 (32 * 64 * 16 + 64 * 64 * 4 + 2 * 64 * 4)   // 49664 B
__global__ __launch_bounds__(128) void k_gemm1(
    const float* __restrict__ x,
    const float* __restrict__ W1p, const float* __restrict__ b1p,
    const float* __restrict__ W1n, const float* __restrict__ b1n, int n)
{
    extern __shared__ char sm[];
    ulonglong2* ws = (ulonglong2*)sm;                       // [32 k2][64 c]
    float* xs  = (float*)(sm + 32 * 64 * 16);               // [64 r][64 k]
    float* sdp = (float*)(sm + 32 * 64 * 16 + 64 * 64 * 4); // [64]
    float* sdn = sdp + 64;

    const int tid = threadIdx.x;
    const int tx = tid & 63;
    const int ty = tid >> 6;
    const int rb  = blockIdx.x >> 1;
    const int colbase = (blockIdx.x & 1) * 64;
    const int base = rb * 64;

    for (int i = tid; i < 16 * 64; i += 128) {
        int k4 = i & 15;
        int c  = i >> 4;
        int col = colbase + c;
        float4 wp = *(const float4*)&W1p[col * IN_ + 4 * k4];
        float4 wn = *(const float4*)&W1n[col * IN_ + 4 * k4];
        int k2a = 2 * k4, k2b = 2 * k4 + 1;
        ws[k2a * 64 + (c ^ (k2a & 15))] =
            make_ulonglong2(packf2(wp.x, wp.y), packf2(wn.x, wn.y));
        ws[k2b * 64 + (c ^ (k2b & 15))] =
            make_ulonglong2(packf2(wp.z, wp.w), packf2(wn.z, wn.w));
    }
    for (int i = tid; i < 64 * 16; i += 128) {
        int r = i >> 4;
        int row = base + r;
        float4 v = make_float4(0.f, 0.f, 0.f, 0.f);
        if (row < n) v = ((const float4*)x)[row * 16 + (i & 15)];
        ((float4*)xs)[i] = v;
    }
    if (tid < 64) {
        int row = base + tid;
        sdp[tid] = (row < n) ? g_dinvp[row] : 0.f;
        sdn[tid] = (row < n) ? g_dinvn[row] : 0.f;
    }
    __syncthreads();

    const int col = colbase + tx;
    const float bp = b1p[col], bn = b1n[col];

    for (int chunk = 0; chunk < 4; chunk++) {
        const int rbase = ty * 32 + chunk * 8;
        const float* xrow = xs + rbase * 64;
        unsigned long long accp[8], accn[8];
        #pragma unroll
        for (int r = 0; r < 8; r++) { accp[r] = 0ull; accn[r] = 0ull; }

        #pragma unroll 4
        for (int k4 = 0; k4 < 16; k4++) {
            const int k2a = 2 * k4, k2b = 2 * k4 + 1;
            ulonglong2 w0 = ws[k2a * 64 + (tx ^ (k2a & 15))];
            ulonglong2 w1 = ws[k2b * 64 + (tx ^ (k2b & 15))];
            #pragma unroll
            for (int r = 0; r < 8; r++) {
                float4 xv = *(const float4*)&xrow[r * 64 + 4 * k4];
                unsigned long long x0 = packf2(xv.x, xv.y);
                unsigned long long x1 = packf2(xv.z, xv.w);
                fma2(accp[r], w0.x, x0);
                fma2(accn[r], w0.y, x0);
                fma2(accp[r], w1.x, x1);
                fma2(accn[r], w1.y, x1);
            }
        }

        #pragma unroll
        for (int r = 0; r < 8; r++) {
            int rr = rbase + r;
            int row = base + rr;
            if (row >= n) continue;
            float pl, ph, ql, qh;
            unpack2(accp[r], pl, ph);
            unpack2(accn[r], ql, qh);
            float ap = pl + ph, an = ql + qh;
            float dp = sdp[rr], dn = sdn[rr];
            g_hps[row * H_ + col] = ap * dp;
            g_hns[row * H_ + col] = an * dn;
            g_h  [row * H_ + col] = ap * dp * dp + bp - an * dn * dn - bn;
        }
    }
}

// ---------------- edge aggregation layer 1: warp per node (F=128) ---------------
__global__ __launch_bounds__(256) void k_edge1(int n)
{
    int v = (blockIdx.x * blockDim.x + threadIdx.x) >> 5;
    if (v >= n) return;
    int lane = threadIdx.x & 31;
    int beg = g_off[v], end = g_off[v + 1];
    float4 acc = *(float4*)&g_h[v * H_ + lane * 4];   // self-loop + bias init
    for (int i = beg; i < end; i++) {
        int2 er = __ldg(&g_eidx[i]);
        float scale = __int_as_float(er.y);
        const float* src = (scale >= 0.f) ? g_hps : g_hns;
        float4 xv = __ldg((const float4*)(src + er.x * H_) + lane);
        acc.x += xv.x * scale; acc.y += xv.y * scale;
        acc.z += xv.z * scale; acc.w += xv.w * scale;
    }
    *(float4*)&g_h[v * H_ + lane * 4] = acc;
}

// ================ GEMM layer 2: relu(h)[N,128] -> (gps,gns,out)[N,64] ============
#define SMEM2 (64 * 64 * 16 + 64 * 128 * 4 + 2 * 64 * 4)   // 98816 B
__global__ __launch_bounds__(128) void k_gemm2(
    const float* __restrict__ W2p, const float* __restrict__ b2p,
    const float* __restrict__ W2n, const float* __restrict__ b2n,
    float* __restrict__ out, int n)
{
    extern __shared__ char sm[];
    ulonglong2* ws = (ulonglong2*)sm;                        // [64 k2][64 c]
    float* xs  = (float*)(sm + 64 * 64 * 16);                // [64 r][128 k]
    float* sdp = (float*)(sm + 64 * 64 * 16 + 64 * 128 * 4); // [64]
    float* sdn = sdp + 64;

    const int tid = threadIdx.x;
    const int tx = tid & 63;
    const int ty = tid >> 6;
    const int base = blockIdx.x * 64;

    for (int i = tid; i < 32 * 64; i += 128) {
        int k4 = i & 31;
        int c  = i >> 5;
        float4 wp = *(const float4*)&W2p[c * H_ + 4 * k4];
        float4 wn = *(const float4*)&W2n[c * H_ + 4 * k4];
        int k2a = 2 * k4, k2b = 2 * k4 + 1;
        ws[k2a * 64 + (c ^ (k2a & 15))] =
            make_ulonglong2(packf2(wp.x, wp.y), packf2(wn.x, wn.y));
        ws[k2b * 64 + (c ^ (k2b & 15))] =
            make_ulonglong2(packf2(wp.z, wp.w), packf2(wn.z, wn.w));
    }
    for (int i = tid; i < 64 * 32; i += 128) {
        int r = i >> 5;
        int row = base + r;
        float4 v = make_float4(0.f, 0.f, 0.f, 0.f);
        if (row < n) {
            v = ((const float4*)g_h)[row * 32 + (i & 31)];
            v.x = fmaxf(v.x, 0.f); v.y = fmaxf(v.y, 0.f);
            v.z = fmaxf(v.z, 0.f); v.w = fmaxf(v.w, 0.f);
        }
        ((float4*)xs)[i] = v;
    }
    if (tid < 64) {
        int row = base + tid;
        sdp[tid] = (row < n) ? g_dinvp[row] : 0.f;
        sdn[tid] = (row < n) ? g_dinvn[row] : 0.f;
    }
    __syncthreads();

    const float bp = b2p[tx], bn = b2n[tx];

    for (int chunk = 0; chunk < 4; chunk++) {
        const int rbase = ty * 32 + chunk * 8;
        const float* xrow = xs + rbase * 128;
        unsigned long long accp[8], accn[8];
        #pragma unroll
        for (int r = 0; r < 8; r++) { accp[r] = 0ull; accn[r] = 0ull; }

        #pragma unroll 8
        for (int k4 = 0; k4 < 32; k4++) {
            const int k2a = 2 * k4, k2b = 2 * k4 + 1;
            ulonglong2 w0 = ws[k2a * 64 + (tx ^ (k2a & 15))];
            ulonglong2 w1 = ws[k2b * 64 + (tx ^ (k2b & 15))];
            #pragma unroll
            for (int r = 0; r < 8; r++) {
                float4 xv = *(const float4*)&xrow[r * 128 + 4 * k4];
                unsigned long long x0 = packf2(xv.x, xv.y);
                unsigned long long x1 = packf2(xv.z, xv.w);
                fma2(accp[r], w0.x, x0);
                fma2(accn[r], w0.y, x0);
                fma2(accp[r], w1.x, x1);
                fma2(accn[r], w1.y, x1);
            }
        }

        #pragma unroll
        for (int r = 0; r < 8; r++) {
            int rr = rbase + r;
            int row = base + rr;
            if (row >= n) continue;
            float pl, ph, ql, qh;
            unpack2(accp[r], pl, ph);
            unpack2(accn[r], ql, qh);
            float ap = pl + ph, an = ql + qh;
            float dp = sdp[rr], dn = sdn[rr];
            g_gps[row * O_ + tx] = ap * dp;
            g_gns[row * O_ + tx] = an * dn;
            out  [row * O_ + tx] = ap * dp * dp + bp - an * dn * dn - bn;
        }
    }
}

// ---------------- edge aggregation layer 2: warp per node (F=64), fused ReLU ----
__global__ __launch_bounds__(256) void k_edge2(float* __restrict__ out, int n)
{
    int v = (blockIdx.x * blockDim.x + threadIdx.x) >> 5;
    if (v >= n) return;
    int lane = threadIdx.x & 31;
    int half = lane >> 4;      // 0: even edges, 1: odd edges
    int f = lane & 15;         // feature group (4 floats each)
    int beg = g_off[v], end = g_off[v + 1];
    float4 acc = make_float4(0.f, 0.f, 0.f, 0.f);
    for (int i = beg + half; i < end; i += 2) {
        int2 er = __ldg(&g_eidx[i]);
        float scale = __int_as_float(er.y);
        const float* src = (scale >= 0.f) ? g_gps : g_gns;
        float4 xv = __ldg((const float4*)(src + er.x * O_) + f);
        acc.x += xv.x * scale; acc.y += xv.y * scale;
        acc.z += xv.z * scale; acc.w += xv.w * scale;
    }
    __syncwarp();
    acc.x += __shfl_xor_sync(~0u, acc.x, 16);
    acc.y += __shfl_xor_sync(~0u, acc.y, 16);
    acc.z += __shfl_xor_sync(~0u, acc.z, 16);
    acc.w += __shfl_xor_sync(~0u, acc.w, 16);
    if (half == 0) {
        float4 self = *(float4*)&out[v * O_ + f * 4];   // self + bias from gemm2
        acc.x = fmaxf(acc.x + self.x, 0.f);
        acc.y = fmaxf(acc.y + self.y, 0.f);
        acc.z = fmaxf(acc.z + self.z, 0.f);
        acc.w = fmaxf(acc.w + self.w, 0.f);
        *(float4*)&out[v * O_ + f * 4] = acc;
    }
}

// ---------------- launch ---------------------------------------------------------
extern "C" void kernel_launch(void* const* d_in, const int* in_sizes, int n_in,
                              void* d_out, int out_size)
{
    const float* x   = (const float*)d_in[0];
    const int*   ei  = (const int*)  d_in[1];
    const float* w   = (const float*)d_in[2];
    const float* W1p = (const float*)d_in[3];
    const float* b1p = (const float*)d_in[4];
    const float* W1n = (const float*)d_in[5];
    const float* b1n = (const float*)d_in[6];
    const float* W2p = (const float*)d_in[7];
    const float* b2p = (const float*)d_in[8];
    const float* W2n = (const float*)d_in[9];
    const float* b2n = (const float*)d_in[10];
    float* out = (float*)d_out;

    const int n = in_sizes[0] / IN_;
    const int E = in_sizes[2];
    const int rowBlocks = (n + 63) / 64;
    const int scanBlocks = (n + SCAN_BLK - 1) / SCAN_BLK;

    cudaFuncSetAttribute(k_gemm1, cudaFuncAttributeMaxDynamicSharedMemorySize, SMEM1);
    cudaFuncSetAttribute(k_gemm2, cudaFuncAttributeMaxDynamicSharedMemorySize, SMEM2);

    k_zero<<<(n + 255) / 256, 256>>>(n);
    k_deg<<<(E + 255) / 256, 256>>>(ei, w, E);
    k_dinv<<<(n + 255) / 256, 256>>>(n);
    k_bsum<<<scanBlocks, 256>>>(n);
    k_bscan<<<1, 128>>>(scanBlocks, n);
    k_offsets<<<scanBlocks, 256>>>(n);
    k_scatter<<<(E + 255) / 256, 256>>>(ei, w, E);

    k_gemm1<<<rowBlocks * 2, 128, SMEM1>>>(x, W1p, b1p, W1n, b1n, n);
    k_edge1<<<(n * 32 + 255) / 256, 256>>>(n);

    k_gemm2<<<rowBlocks, 128, SMEM2>>>(W2p, b2p, W2n, b2n, out, n);
    k_edge2<<<(n * 32 + 255) / 256, 256>>>(out, n);
}

// round 9
// speedup vs baseline: 2.8743x; 1.1397x over previous
#include <cuda_runtime.h>
#include <cuda_bf16.h>

#define N_   100000
#define E_   1600000
#define IN_  64
#define H_   128
#define O_   64
#define SCAN_BLK 1024

// ---------------- scratch -------------------------------------------------------
__device__ float g_degp[N_];
__device__ float g_degn[N_];
__device__ float g_dinvp[N_];
__device__ float g_dinvn[N_];
__device__ int   g_cnt [N_];
__device__ int   g_cur [N_];
__device__ int   g_off [N_ + 1];
__device__ int   g_bsum[(N_ + SCAN_BLK - 1) / SCAN_BLK];
__device__ int   g_bpre[(N_ + SCAN_BLK - 1) / SCAN_BLK];
__device__ int2  g_eidx[E_];
__device__ float g_hps[N_ * H_];
__device__ float g_hns[N_ * H_];
__device__ float g_h  [N_ * H_];
__device__ float g_gps[N_ * O_];
__device__ float g_gns[N_ * O_];

// ---------------- helpers ------------------------------------------------------
__device__ __forceinline__ void fma2(unsigned long long& acc,
                                     unsigned long long w,
                                     unsigned long long xx) {
    asm("fma.rn.f32x2 %0, %1, %2, %0;" : "+l"(acc) : "l"(w), "l"(xx));
}

__device__ __forceinline__ unsigned long long packf2(float a, float b) {
    unsigned long long r;
    asm("mov.b64 %0, {%1, %2};" : "=l"(r) : "f"(a), "f"(b));
    return r;
}

__device__ __forceinline__ void unpack2(unsigned long long v, float& lo, float& hi) {
    asm("mov.b64 {%0, %1}, %2;" : "=f"(lo), "=f"(hi) : "l"(v));
}

// ---------------- degree / dinv / CSR build -------------------------------------
__global__ void k_zero(int n) {
    int i = blockIdx.x * blockDim.x + threadIdx.x;
    if (i < n) { g_degp[i] = 0.f; g_degn[i] = 0.f; g_cnt[i] = 0; g_cur[i] = 0; }
}

__global__ void k_deg(const int* __restrict__ ei, const float* __restrict__ w, int E) {
    int e = blockIdx.x * blockDim.x + threadIdx.x;
    if (e >= E) return;
    float we = w[e];
    int t = ei[E + e];
    if (we > 0.f)      atomicAdd(&g_degp[t], we);
    else if (we < 0.f) atomicAdd(&g_degn[t], -we);
    atomicAdd(&g_cnt[t], 1);
}

__global__ void k_dinv(int n) {
    int i = blockIdx.x * blockDim.x + threadIdx.x;
    if (i < n) {
        g_dinvp[i] = rsqrtf(g_degp[i] + 1.0f);
        g_dinvn[i] = rsqrtf(g_degn[i] + 1.0f);
    }
}

__global__ __launch_bounds__(256) void k_bsum(int n) {
    __shared__ int wsum[8];
    const int b = blockIdx.x;
    const int tid = threadIdx.x;
    int s = 0;
    #pragma unroll
    for (int j = 0; j < 4; j++) {
        int i = b * SCAN_BLK + j * 256 + tid;
        if (i < n) s += g_cnt[i];
    }
    #pragma unroll
    for (int o = 16; o > 0; o >>= 1) s += __shfl_xor_sync(~0u, s, o);
    if ((tid & 31) == 0) wsum[tid >> 5] = s;
    __syncthreads();
    if (tid == 0) {
        int t = 0;
        #pragma unroll
        for (int k = 0; k < 8; k++) t += wsum[k];
        g_bsum[b] = t;
    }
}

__global__ __launch_bounds__(128) void k_bscan(int B, int n) {
    __shared__ int sh[1024];
    for (int i = threadIdx.x; i < B; i += 128) sh[i] = g_bsum[i];
    __syncthreads();
    if (threadIdx.x == 0) {
        int run = 0;
        for (int i = 0; i < B; i++) { int v = sh[i]; sh[i] = run; run += v; }
        g_off[n] = run;
    }
    __syncthreads();
    for (int i = threadIdx.x; i < B; i += 128) g_bpre[i] = sh[i];
}

__global__ __launch_bounds__(256) void k_offsets(int n) {
    __shared__ int wsum[8];
    const int b = blockIdx.x;
    const int tid = threadIdx.x;
    const int lane = tid & 31;
    const int wid = tid >> 5;
    const int i0 = b * SCAN_BLK + tid * 4;

    int c0 = 0, c1 = 0, c2 = 0, c3 = 0;
    if (i0 + 3 < n) {
        int4 c = *(const int4*)&g_cnt[i0];
        c0 = c.x; c1 = c.y; c2 = c.z; c3 = c.w;
    } else {
        if (i0     < n) c0 = g_cnt[i0];
        if (i0 + 1 < n) c1 = g_cnt[i0 + 1];
        if (i0 + 2 < n) c2 = g_cnt[i0 + 2];
        if (i0 + 3 < n) c3 = g_cnt[i0 + 3];
    }
    int tsum = c0 + c1 + c2 + c3;

    int x = tsum;
    #pragma unroll
    for (int o = 1; o < 32; o <<= 1) {
        int y = __shfl_up_sync(~0u, x, o);
        if (lane >= o) x += y;
    }
    if (lane == 31) wsum[wid] = x;
    __syncthreads();
    if (tid == 0) {
        int run = 0;
        #pragma unroll
        for (int k = 0; k < 8; k++) { int v = wsum[k]; wsum[k] = run; run += v; }
    }
    __syncthreads();

    int pre = g_bpre[b] + wsum[wid] + (x - tsum);
    if (i0 + 3 < n) {
        int4 o4 = make_int4(pre, pre + c0, pre + c0 + c1, pre + c0 + c1 + c2);
        *(int4*)&g_off[i0] = o4;
    } else {
        if (i0     < n) g_off[i0]     = pre;
        if (i0 + 1 < n) g_off[i0 + 1] = pre + c0;
        if (i0 + 2 < n) g_off[i0 + 2] = pre + c0 + c1;
        if (i0 + 3 < n) g_off[i0 + 3] = pre + c0 + c1 + c2;
    }
}

__global__ void k_scatter(const int* __restrict__ ei, const float* __restrict__ w, int E) {
    int e = blockIdx.x * blockDim.x + threadIdx.x;
    if (e >= E) return;
    int s = ei[e];
    int t = ei[E + e];
    float we = w[e];
    float d = (we >= 0.f) ? g_dinvp[t] : g_dinvn[t];
    int pos = g_off[t] + atomicAdd(&g_cur[t], 1);
    g_eidx[pos] = make_int2(s, __float_as_int(we * d));
}

// ================ GEMM layer 1: x[N,64] -> (hps,hns,h)[N,128] ====================
// 256 threads: tx=tid&63 (col), ty=tid>>6 (0..3 -> 16 rows each, 2 chunks of 8)
#define SMEM1 (32 * 64 * 16 + 64 * 64 * 4 + 2 * 64 * 4)   // 49664 B
__global__ __launch_bounds__(256) void k_gemm1(
    const float* __restrict__ x,
    const float* __restrict__ W1p, const float* __restrict__ b1p,
    const float* __restrict__ W1n, const float* __restrict__ b1n, int n)
{
    extern __shared__ char sm[];
    ulonglong2* ws = (ulonglong2*)sm;                       // [32 k2][64 c]
    float* xs  = (float*)(sm + 32 * 64 * 16);               // [64 r][64 k]
    float* sdp = (float*)(sm + 32 * 64 * 16 + 64 * 64 * 4); // [64]
    float* sdn = sdp + 64;

    const int tid = threadIdx.x;
    const int tx = tid & 63;
    const int ty = tid >> 6;
    const int rb  = blockIdx.x >> 1;
    const int colbase = (blockIdx.x & 1) * 64;
    const int base = rb * 64;

    for (int i = tid; i < 16 * 64; i += 256) {
        int k4 = i & 15;
        int c  = i >> 4;
        int col = colbase + c;
        float4 wp = *(const float4*)&W1p[col * IN_ + 4 * k4];
        float4 wn = *(const float4*)&W1n[col * IN_ + 4 * k4];
        int k2a = 2 * k4, k2b = 2 * k4 + 1;
        ws[k2a * 64 + (c ^ (k2a & 15))] =
            make_ulonglong2(packf2(wp.x, wp.y), packf2(wn.x, wn.y));
        ws[k2b * 64 + (c ^ (k2b & 15))] =
            make_ulonglong2(packf2(wp.z, wp.w), packf2(wn.z, wn.w));
    }
    for (int i = tid; i < 64 * 16; i += 256) {
        int r = i >> 4;
        int row = base + r;
        float4 v = make_float4(0.f, 0.f, 0.f, 0.f);
        if (row < n) v = ((const float4*)x)[row * 16 + (i & 15)];
        ((float4*)xs)[i] = v;
    }
    if (tid < 64) {
        int row = base + tid;
        sdp[tid] = (row < n) ? g_dinvp[row] : 0.f;
        sdn[tid] = (row < n) ? g_dinvn[row] : 0.f;
    }
    __syncthreads();

    const int col = colbase + tx;
    const float bp = b1p[col], bn = b1n[col];

    for (int chunk = 0; chunk < 2; chunk++) {
        const int rbase = ty * 16 + chunk * 8;
        const float* xrow = xs + rbase * 64;
        unsigned long long accp[8], accn[8];
        #pragma unroll
        for (int r = 0; r < 8; r++) { accp[r] = 0ull; accn[r] = 0ull; }

        #pragma unroll 4
        for (int k4 = 0; k4 < 16; k4++) {
            const int k2a = 2 * k4, k2b = 2 * k4 + 1;
            ulonglong2 w0 = ws[k2a * 64 + (tx ^ (k2a & 15))];
            ulonglong2 w1 = ws[k2b * 64 + (tx ^ (k2b & 15))];
            #pragma unroll
            for (int r = 0; r < 8; r++) {
                float4 xv = *(const float4*)&xrow[r * 64 + 4 * k4];
                unsigned long long x0 = packf2(xv.x, xv.y);
                unsigned long long x1 = packf2(xv.z, xv.w);
                fma2(accp[r], w0.x, x0);
                fma2(accn[r], w0.y, x0);
                fma2(accp[r], w1.x, x1);
                fma2(accn[r], w1.y, x1);
            }
        }

        #pragma unroll
        for (int r = 0; r < 8; r++) {
            int rr = rbase + r;
            int row = base + rr;
            if (row >= n) continue;
            float pl, ph, ql, qh;
            unpack2(accp[r], pl, ph);
            unpack2(accn[r], ql, qh);
            float ap = pl + ph, an = ql + qh;
            float dp = sdp[rr], dn = sdn[rr];
            g_hps[row * H_ + col] = ap * dp;
            g_hns[row * H_ + col] = an * dn;
            g_h  [row * H_ + col] = ap * dp * dp + bp - an * dn * dn - bn;
        }
    }
}

// ---------------- edge aggregation layer 1: warp per node (F=128) ---------------
__global__ __launch_bounds__(256) void k_edge1(int n)
{
    int v = (blockIdx.x * blockDim.x + threadIdx.x) >> 5;
    if (v >= n) return;
    int lane = threadIdx.x & 31;
    int beg = g_off[v], end = g_off[v + 1];
    float4 acc = *(float4*)&g_h[v * H_ + lane * 4];
    for (int i = beg; i < end; i++) {
        int2 er = __ldg(&g_eidx[i]);
        float scale = __int_as_float(er.y);
        const float* src = (scale >= 0.f) ? g_hps : g_hns;
        float4 xv = __ldg((const float4*)(src + er.x * H_) + lane);
        acc.x += xv.x * scale; acc.y += xv.y * scale;
        acc.z += xv.z * scale; acc.w += xv.w * scale;
    }
    *(float4*)&g_h[v * H_ + lane * 4] = acc;
}

// ================ GEMM layer 2: relu(h)[N,128] -> (gps,gns,out)[N,64] ============
// 256 threads: tx=tid&63 (col), ty=tid>>6 (16 rows each, 2 chunks of 8)
#define SMEM2 (64 * 64 * 16 + 64 * 128 * 4 + 2 * 64 * 4)   // 98816 B
__global__ __launch_bounds__(256) void k_gemm2(
    const float* __restrict__ W2p, const float* __restrict__ b2p,
    const float* __restrict__ W2n, const float* __restrict__ b2n,
    float* __restrict__ out, int n)
{
    extern __shared__ char sm[];
    ulonglong2* ws = (ulonglong2*)sm;                        // [64 k2][64 c]
    float* xs  = (float*)(sm + 64 * 64 * 16);                // [64 r][128 k]
    float* sdp = (float*)(sm + 64 * 64 * 16 + 64 * 128 * 4); // [64]
    float* sdn = sdp + 64;

    const int tid = threadIdx.x;
    const int tx = tid & 63;
    const int ty = tid >> 6;
    const int base = blockIdx.x * 64;

    for (int i = tid; i < 32 * 64; i += 256) {
        int k4 = i & 31;
        int c  = i >> 5;
        float4 wp = *(const float4*)&W2p[c * H_ + 4 * k4];
        float4 wn = *(const float4*)&W2n[c * H_ + 4 * k4];
        int k2a = 2 * k4, k2b = 2 * k4 + 1;
        ws[k2a * 64 + (c ^ (k2a & 15))] =
            make_ulonglong2(packf2(wp.x, wp.y), packf2(wn.x, wn.y));
        ws[k2b * 64 + (c ^ (k2b & 15))] =
            make_ulonglong2(packf2(wp.z, wp.w), packf2(wn.z, wn.w));
    }
    for (int i = tid; i < 64 * 32; i += 256) {
        int r = i >> 5;
        int row = base + r;
        float4 v = make_float4(0.f, 0.f, 0.f, 0.f);
        if (row < n) {
            v = ((const float4*)g_h)[row * 32 + (i & 31)];
            v.x = fmaxf(v.x, 0.f); v.y = fmaxf(v.y, 0.f);
            v.z = fmaxf(v.z, 0.f); v.w = fmaxf(v.w, 0.f);
        }
        ((float4*)xs)[i] = v;
    }
    if (tid < 64) {
        int row = base + tid;
        sdp[tid] = (row < n) ? g_dinvp[row] : 0.f;
        sdn[tid] = (row < n) ? g_dinvn[row] : 0.f;
    }
    __syncthreads();

    const float bp = b2p[tx], bn = b2n[tx];

    for (int chunk = 0; chunk < 2; chunk++) {
        const int rbase = ty * 16 + chunk * 8;
        const float* xrow = xs + rbase * 128;
        unsigned long long accp[8], accn[8];
        #pragma unroll
        for (int r = 0; r < 8; r++) { accp[r] = 0ull; accn[r] = 0ull; }

        #pragma unroll 8
        for (int k4 = 0; k4 < 32; k4++) {
            const int k2a = 2 * k4, k2b = 2 * k4 + 1;
            ulonglong2 w0 = ws[k2a * 64 + (tx ^ (k2a & 15))];
            ulonglong2 w1 = ws[k2b * 64 + (tx ^ (k2b & 15))];
            #pragma unroll
            for (int r = 0; r < 8; r++) {
                float4 xv = *(const float4*)&xrow[r * 128 + 4 * k4];
                unsigned long long x0 = packf2(xv.x, xv.y);
                unsigned long long x1 = packf2(xv.z, xv.w);
                fma2(accp[r], w0.x, x0);
                fma2(accn[r], w0.y, x0);
                fma2(accp[r], w1.x, x1);
                fma2(accn[r], w1.y, x1);
            }
        }

        #pragma unroll
        for (int r = 0; r < 8; r++) {
            int rr = rbase + r;
            int row = base + rr;
            if (row >= n) continue;
            float pl, ph, ql, qh;
            unpack2(accp[r], pl, ph);
            unpack2(accn[r], ql, qh);
            float ap = pl + ph, an = ql + qh;
            float dp = sdp[rr], dn = sdn[rr];
            g_gps[row * O_ + tx] = ap * dp;
            g_gns[row * O_ + tx] = an * dn;
            out  [row * O_ + tx] = ap * dp * dp + bp - an * dn * dn - bn;
        }
    }
}

// ---------------- edge aggregation layer 2: warp per node (F=64), fused ReLU ----
__global__ __launch_bounds__(256) void k_edge2(float* __restrict__ out, int n)
{
    int v = (blockIdx.x * blockDim.x + threadIdx.x) >> 5;
    if (v >= n) return;
    int lane = threadIdx.x & 31;
    int half = lane >> 4;
    int f = lane & 15;
    int beg = g_off[v], end = g_off[v + 1];
    float4 acc = make_float4(0.f, 0.f, 0.f, 0.f);
    for (int i = beg + half; i < end; i += 2) {
        int2 er = __ldg(&g_eidx[i]);
        float scale = __int_as_float(er.y);
        const float* src = (scale >= 0.f) ? g_gps : g_gns;
        float4 xv = __ldg((const float4*)(src + er.x * O_) + f);
        acc.x += xv.x * scale; acc.y += xv.y * scale;
        acc.z += xv.z * scale; acc.w += xv.w * scale;
    }
    __syncwarp();
    acc.x += __shfl_xor_sync(~0u, acc.x, 16);
    acc.y += __shfl_xor_sync(~0u, acc.y, 16);
    acc.z += __shfl_xor_sync(~0u, acc.z, 16);
    acc.w += __shfl_xor_sync(~0u, acc.w, 16);
    if (half == 0) {
        float4 self = *(float4*)&out[v * O_ + f * 4];
        acc.x = fmaxf(acc.x + self.x, 0.f);
        acc.y = fmaxf(acc.y + self.y, 0.f);
        acc.z = fmaxf(acc.z + self.z, 0.f);
        acc.w = fmaxf(acc.w + self.w, 0.f);
        *(float4*)&out[v * O_ + f * 4] = acc;
    }
}

// ---------------- launch ---------------------------------------------------------
extern "C" void kernel_launch(void* const* d_in, const int* in_sizes, int n_in,
                              void* d_out, int out_size)
{
    const float* x   = (const float*)d_in[0];
    const int*   ei  = (const int*)  d_in[1];
    const float* w   = (const float*)d_in[2];
    const float* W1p = (const float*)d_in[3];
    const float* b1p = (const float*)d_in[4];
    const float* W1n = (const float*)d_in[5];
    const float* b1n = (const float*)d_in[6];
    const float* W2p = (const float*)d_in[7];
    const float* b2p = (const float*)d_in[8];
    const float* W2n = (const float*)d_in[9];
    const float* b2n = (const float*)d_in[10];
    float* out = (float*)d_out;

    const int n = in_sizes[0] / IN_;
    const int E = in_sizes[2];
    const int rowBlocks = (n + 63) / 64;
    const int scanBlocks = (n + SCAN_BLK - 1) / SCAN_BLK;

    cudaFuncSetAttribute(k_gemm1, cudaFuncAttributeMaxDynamicSharedMemorySize, SMEM1);
    cudaFuncSetAttribute(k_gemm2, cudaFuncAttributeMaxDynamicSharedMemorySize, SMEM2);

    k_zero<<<(n + 255) / 256, 256>>>(n);
    k_deg<<<(E + 255) / 256, 256>>>(ei, w, E);
    k_dinv<<<(n + 255) / 256, 256>>>(n);
    k_bsum<<<scanBlocks, 256>>>(n);
    k_bscan<<<1, 128>>>(scanBlocks, n);
    k_offsets<<<scanBlocks, 256>>>(n);
    k_scatter<<<(E + 255) / 256, 256>>>(ei, w, E);

    k_gemm1<<<rowBlocks * 2, 256, SMEM1>>>(x, W1p, b1p, W1n, b1n, n);
    k_edge1<<<(n * 32 + 255) / 256, 256>>>(n);

    k_gemm2<<<rowBlocks, 256, SMEM2>>>(W2p, b2p, W2n, b2n, out, n);
    k_edge2<<<(n * 32 + 255) / 256, 256>>>(out, n);
}